// round 4
// baseline (speedup 1.0000x reference)
#include <cuda_runtime.h>
#include <math.h>

#define L     4096
#define CCH   128
#define DI    256
#define NDIR  3
#define LT    (NDIR*L)
#define DS    16
#define NCHUNK 64
#define CHLEN  64
#define CTL   16
#define NM40  (LT*40)

// ---------------- scratch ----------------
__device__ float g_xT[L*CCH];
__device__ float g_tok[L*CCH];
__device__ float g_xz[L*2*DI];
__device__ float g_xc[LT*DI];         // [lg][d] for x_dbl GEMM
__device__ float g_xcT[DI*LT];        // [d][lg] for scan
__device__ float g_part[4*NM40];      // split-K partials of x_dbl
__device__ float g_BCT[32*LT];        // rows 0..15 = B^T, 16..31 = C^T  [n][lg]
__device__ float g_deltaT[DI*LT];     // [d][lg]
__device__ float g_y[LT*DI];          // scan output (ungated, +D skip)
__device__ float g_mo[LT*CCH];
__device__ float g_resT[L*CCH];
__device__ float g_hid[L*512];

typedef unsigned long long u64;

__device__ __forceinline__ void ffma2(u64 &d, u64 a, u64 b){
    asm("fma.rn.f32x2 %0, %1, %2, %0;" : "+l"(d) : "l"(a), "l"(b));
}
__device__ __forceinline__ void unpack2(u64 v, float &lo, float &hi){
    asm("mov.b64 {%0, %1}, %2;" : "=f"(lo), "=f"(hi) : "l"(v));
}

__device__ __forceinline__ int ptok(int dir, int l){
    int a = l >> 8, b = (l >> 4) & 15, c = l & 15;
    if (dir == 0) return l;
    if (dir == 1) return c*256 + a*16 + b;
    return b*256 + c*16 + a;
}
__device__ __forceinline__ int stol(int dir, int s){
    int a = s >> 8, b = (s >> 4) & 15, cc = s & 15;
    if (dir == 0) return s;
    if (dir == 1) return b*256 + cc*16 + a;
    return cc*256 + a*16 + b;
}

// ---------------- K1: fused transpose + double LayerNorm ----------------
__global__ void k_lnx(const float* __restrict__ x,
                      const float* __restrict__ lnw, const float* __restrict__ lnb,
                      const float* __restrict__ mw,  const float* __restrict__ mb){
    __shared__ float t[128][33];
    int s0 = blockIdx.x*32;
    int lane = threadIdx.x & 31, w = threadIdx.x >> 5;
    for (int r = w; r < 128; r += 8)
        t[r][lane] = x[(size_t)r*L + s0 + lane];
    __syncthreads();
    for (int round = 0; round < 4; round++){
        int tloc = round*8 + w;
        int s = s0 + tloc;
        float v[4];
        #pragma unroll
        for (int i = 0; i < 4; i++) v[i] = t[lane + 32*i][tloc];
        #pragma unroll
        for (int i = 0; i < 4; i++) g_xT[(size_t)s*CCH + lane + 32*i] = v[i];
        float sum = v[0]+v[1]+v[2]+v[3];
        #pragma unroll
        for (int o = 16; o; o >>= 1) sum += __shfl_xor_sync(0xffffffffu, sum, o);
        float mean = sum * (1.f/128.f);
        float d[4], var = 0.f;
        #pragma unroll
        for (int i = 0; i < 4; i++){ d[i] = v[i]-mean; var += d[i]*d[i]; }
        #pragma unroll
        for (int o = 16; o; o >>= 1) var += __shfl_xor_sync(0xffffffffu, var, o);
        float rs = rsqrtf(var*(1.f/128.f) + 1e-6f);
        float v1[4];
        #pragma unroll
        for (int i = 0; i < 4; i++){
            int c = lane + 32*i;
            v1[i] = d[i]*rs*lnw[c] + lnb[c];
        }
        float sum2 = v1[0]+v1[1]+v1[2]+v1[3];
        #pragma unroll
        for (int o = 16; o; o >>= 1) sum2 += __shfl_xor_sync(0xffffffffu, sum2, o);
        float mean2 = sum2 * (1.f/128.f);
        float d2[4], var2 = 0.f;
        #pragma unroll
        for (int i = 0; i < 4; i++){ d2[i] = v1[i]-mean2; var2 += d2[i]*d2[i]; }
        #pragma unroll
        for (int o = 16; o; o >>= 1) var2 += __shfl_xor_sync(0xffffffffu, var2, o);
        float rs2 = rsqrtf(var2*(1.f/128.f) + 1e-5f);
        #pragma unroll
        for (int i = 0; i < 4; i++){
            int c = lane + 32*i;
            g_tok[(size_t)s*CCH + c] = d2[i]*rs2*mw[c] + mb[c];
        }
    }
}

// ---------------- f32x2 tiled SGEMM with pre-duplicated B ----------------
// AMODE: 0 plain row-major, 1 PERM (3-dir gather from g_mo), 2 GATE (y * silu(z))
template<int TM, int ACT, bool BIAS, bool RES, bool TSTORE, int AMODE, bool SPLITK>
__global__ void k_tgemm(const float* __restrict__ A,
                        const float* __restrict__ W,
                        const float* __restrict__ bias,
                        const float* __restrict__ res,
                        float* __restrict__ out,
                        int N, int K,
                        const float* __restrict__ zsrc){
    constexpr int TN = 64, KS = 16;
    constexpr int NP = TM/32;
    constexpr int AL = (TM + 63)/64;
    __shared__ __align__(16) float As[KS][TM+4];
    __shared__ __align__(16) float Bs2[KS][144];
    int tid = threadIdx.x;
    int tx = tid & 15, ty = tid >> 4;
    int lkq = tid & 3, lm = tid >> 2;
    int m0 = blockIdx.x * TM, n0 = blockIdx.y * TN;

    int kbeg = 0, kend = K;
    if (SPLITK){
        int ksz = K / gridDim.z;
        kbeg = blockIdx.z * ksz;
        kend = kbeg + ksz;
    }

    u64 acc[NP][4];
    #pragma unroll
    for (int p = 0; p < NP; p++)
        #pragma unroll
        for (int j = 0; j < 4; j++) acc[p][j] = 0ull;

    float4 ra[AL]; float4 rb;
    auto loadA = [&](int m, int k)->float4{
        if (AMODE == 1){
            int dir = k >> 7, c = k & 127;
            int l = stol(dir, m);
            return *(const float4*)(A + ((size_t)(dir*L + l)*CCH + c));
        } else if (AMODE == 2){
            int dir = m >> 12, l = m & 4095;
            int tok = ptok(dir, l);
            float4 y = *(const float4*)(A + (size_t)m*K + k);
            float4 z = *(const float4*)(zsrc + (size_t)tok*512 + 256 + k);
            y.x *= z.x / (1.f + __expf(-z.x));
            y.y *= z.y / (1.f + __expf(-z.y));
            y.z *= z.z / (1.f + __expf(-z.z));
            y.w *= z.w / (1.f + __expf(-z.w));
            return y;
        }
        return *(const float4*)(A + (size_t)m*K + k);
    };
    auto loadTile = [&](int k0){
        #pragma unroll
        for (int i = 0; i < AL; i++){
            int m = lm + i*64;
            if (m < TM) ra[i] = loadA(m0 + m, k0 + lkq*4);
        }
        int n = n0 + lm;
        rb = make_float4(0.f,0.f,0.f,0.f);
        if (n < N) rb = *(const float4*)(W + (size_t)n*K + k0 + lkq*4);
    };
    int bpos = (lm>>2)*8 + (lm>>4)*4 + (lm&3)*2;   // swizzled dup-pair slot for n=lm
    auto storeTile = [&](){
        #pragma unroll
        for (int i = 0; i < AL; i++){
            int m = lm + i*64;
            if (m < TM){
                As[lkq*4+0][m] = ra[i].x; As[lkq*4+1][m] = ra[i].y;
                As[lkq*4+2][m] = ra[i].z; As[lkq*4+3][m] = ra[i].w;
            }
        }
        const float* rv = &rb.x;
        #pragma unroll
        for (int q = 0; q < 4; q++)
            *(float2*)&Bs2[lkq*4+q][bpos] = make_float2(rv[q], rv[q]);
    };

    int NT = (kend - kbeg) / KS;
    loadTile(kbeg);
    for (int t = 0; t < NT; t++){
        storeTile();
        __syncthreads();
        if (t + 1 < NT) loadTile(kbeg + (t+1)*KS);
        int bbase = tx*8 + (tx>>2)*4;
        #pragma unroll
        for (int kk = 0; kk < KS; kk++){
            const u64* bp = (const u64*)&Bs2[kk][bbase];
            u64 bd[4];
            bd[0] = bp[0]; bd[1] = bp[1]; bd[2] = bp[2]; bd[3] = bp[3];
            u64 ap[NP];
            if (TM == 32){
                ap[0] = *(const u64*)&As[kk][ty*2];
            } else if (TM == 64){
                const u64* p = (const u64*)&As[kk][ty*4];
                ap[0] = p[0]; ap[1] = p[1];
            } else {
                const u64* p0 = (const u64*)&As[kk][ty*4];
                const u64* p1 = (const u64*)&As[kk][64 + ty*4];
                ap[0] = p0[0]; ap[1] = p0[1]; ap[2] = p1[0]; ap[3] = p1[1];
            }
            #pragma unroll
            for (int p = 0; p < NP; p++)
                #pragma unroll
                for (int j = 0; j < 4; j++)
                    ffma2(acc[p][j], ap[p], bd[j]);
        }
        __syncthreads();
    }

    size_t zoff = 0;
    if (SPLITK) zoff = (size_t)blockIdx.z * gridDim.x * TM * N;

    #pragma unroll
    for (int p = 0; p < NP; p++){
        int rbase = (TM == 32) ? ty*2
                  : (TM == 64) ? ty*4 + p*2
                  : (p >> 1)*64 + ty*4 + (p & 1)*2;
        #pragma unroll
        for (int j = 0; j < 4; j++){
            int n = n0 + tx*4 + j;
            if (n >= N) continue;
            float lo, hi;
            unpack2(acc[p][j], lo, hi);
            #pragma unroll
            for (int half = 0; half < 2; half++){
                int m = m0 + rbase + half;
                float v = half ? hi : lo;
                if (SPLITK){
                    out[zoff + (size_t)m*N + n] = v;
                    continue;
                }
                if (BIAS) v += bias[n];
                if (ACT == 1)      v = v / (1.f + __expf(-v));
                else if (ACT == 2) v = 0.5f * v * (1.f + erff(v * 0.70710678118654752f));
                if (RES) v += res[(size_t)m*N + n];
                if (TSTORE) out[(size_t)n*L + m] = v;
                else        out[(size_t)m*N + n] = v;
            }
        }
    }
}

// ---------------- conv: causal depthwise k=4 + silu, dual-layout store ----------------
__global__ void k_conv(const float* __restrict__ cw, const float* __restrict__ cb){
    __shared__ float sx[CTL+3][DI];
    __shared__ float sy[CTL][260];
    int dir = blockIdx.y, l0 = blockIdx.x*CTL, ch = threadIdx.x;
    for (int r = 0; r < CTL+3; r++){
        int row = l0 - 3 + r;
        sx[r][ch] = (row >= 0) ? g_xz[(size_t)ptok(dir, row)*(2*DI) + ch] : 0.f;
    }
    __syncthreads();
    float w0 = cw[ch*4+0], w1 = cw[ch*4+1], w2 = cw[ch*4+2], w3 = cw[ch*4+3];
    float b = cb[ch];
    for (int i = 0; i < CTL; i++){
        float acc = b + w0*sx[i][ch] + w1*sx[i+1][ch] + w2*sx[i+2][ch] + w3*sx[i+3][ch];
        acc = acc / (1.f + __expf(-acc));
        g_xc[(size_t)(dir*L + l0 + i)*DI + ch] = acc;
        sy[i][ch] = acc;
    }
    __syncthreads();
    int mq = threadIdx.x & 3;
    int chb = threadIdx.x >> 2;
    #pragma unroll
    for (int it = 0; it < 4; it++){
        int c2 = chb + 64*it;
        float4 v;
        v.x = sy[mq*4+0][c2]; v.y = sy[mq*4+1][c2];
        v.z = sy[mq*4+2][c2]; v.w = sy[mq*4+3][c2];
        *(float4*)&g_xcT[(size_t)c2*LT + dir*L + l0 + mq*4] = v;
    }
}

// ---------------- fixup: sum split-K parts, emit B^T/C^T/delta^T ----------------
__global__ void k_fixup(const float* __restrict__ dtw, const float* __restrict__ dtb){
    __shared__ float sdbl[64][41];
    __shared__ float sdel[32][260];
    int tid = threadIdx.x;
    int lg0 = blockIdx.x * 64;
    for (int idx = tid; idx < 64*40; idx += 256){
        int lg = idx / 40, nn = idx % 40;
        float s = 0.f;
        #pragma unroll
        for (int z = 0; z < 4; z++)
            s += g_part[(size_t)z*NM40 + (size_t)(lg0+lg)*40 + nn];
        sdbl[lg][nn] = s;
    }
    __syncthreads();
    // B^T / C^T (rows 0..31 -> cols 8..39)
    {
        int mq = tid & 15, nr = tid >> 4;
        #pragma unroll
        for (int p = 0; p < 2; p++){
            int n = p*16 + nr;
            float4 v;
            v.x = sdbl[mq*4+0][8+n]; v.y = sdbl[mq*4+1][8+n];
            v.z = sdbl[mq*4+2][8+n]; v.w = sdbl[mq*4+3][8+n];
            *(float4*)&g_BCT[(size_t)n*LT + lg0 + mq*4] = v;
        }
    }
    // delta^T
    float wr[8];
    #pragma unroll
    for (int r = 0; r < 8; r++) wr[r] = dtw[tid*8 + r];
    float bb = dtb[tid];
    for (int half = 0; half < 2; half++){
        int lgb = half*32;
        for (int lg = 0; lg < 32; lg++){
            float a = bb;
            #pragma unroll
            for (int r = 0; r < 8; r++) a = fmaf(wr[r], sdbl[lgb+lg][r], a);
            a = (a > 20.f) ? a : log1pf(__expf(a));
            sdel[lg][tid] = a;
        }
        __syncthreads();
        int mq = tid & 7, db = tid >> 3;
        #pragma unroll
        for (int it = 0; it < 8; it++){
            int d = db + 32*it;
            float4 v;
            v.x = sdel[mq*4+0][d]; v.y = sdel[mq*4+1][d];
            v.z = sdel[mq*4+2][d]; v.w = sdel[mq*4+3][d];
            *(float4*)&g_deltaT[(size_t)d*LT + lg0 + lgb + mq*4] = v;
        }
        __syncthreads();
    }
}

// ---------------- fused selective scan (float4-streamed) ----------------
__global__ void __launch_bounds__(1024) k_scan(const float* __restrict__ Alog,
                                               const float* __restrict__ Dp){
    __shared__ float sP[NCHUNK][DS];
    __shared__ float sS[NCHUNK][DS];
    int bx = blockIdx.x;
    int dir = bx >> 8, d = bx & 255;
    int tid = threadIdx.x;
    int chunk = tid >> 4, n = tid & 15;
    float Av = -__expf(Alog[d*DS + n]);
    int base = dir*L + chunk*CHLEN;
    const float* dptr = g_deltaT + (size_t)d*LT + base;
    const float* uptr = g_xcT   + (size_t)d*LT + base;
    const float* bptr = g_BCT   + (size_t)n*LT + base;
    const float* cptr = g_BCT   + (size_t)(16+n)*LT + base;

    // pass A: chunk summaries
    float P = 1.f, S = 0.f;
    for (int s4 = 0; s4 < CHLEN/4; s4++){
        float4 dl4 = *(const float4*)(dptr + s4*4);
        float4 u4  = *(const float4*)(uptr + s4*4);
        float4 B4  = *(const float4*)(bptr + s4*4);
        const float* dl = &dl4.x; const float* uu = &u4.x; const float* BB = &B4.x;
        #pragma unroll
        for (int q = 0; q < 4; q++){
            float a = __expf(dl[q] * Av);
            P *= a;
            S = a*S + dl[q]*BB[q]*uu[q];
        }
    }
    sP[chunk][n] = P; sS[chunk][n] = S;
    __syncthreads();

    // Kogge-Stone inclusive scan over chunks
    #pragma unroll
    for (int off = 1; off < NCHUNK; off <<= 1){
        float pP = 1.f, pS = 0.f;
        if (chunk >= off){ pP = sP[chunk-off][n]; pS = sS[chunk-off][n]; }
        __syncthreads();
        S = fmaf(P, pS, S);
        P *= pP;
        sP[chunk][n] = P; sS[chunk][n] = S;
        __syncthreads();
    }
    float h = (chunk > 0) ? sS[chunk-1][n] : 0.f;

    // pass C
    float Dv = Dp[d];
    for (int s4 = 0; s4 < CHLEN/4; s4++){
        float4 dl4 = *(const float4*)(dptr + s4*4);
        float4 u4  = *(const float4*)(uptr + s4*4);
        float4 B4  = *(const float4*)(bptr + s4*4);
        float4 C4  = *(const float4*)(cptr + s4*4);
        const float* dl = &dl4.x; const float* uu = &u4.x;
        const float* BB = &B4.x;  const float* CC = &C4.x;
        #pragma unroll
        for (int q = 0; q < 4; q++){
            float a = __expf(dl[q] * Av);
            h = a*h + dl[q]*BB[q]*uu[q];
            float p = h * CC[q];
            p += __shfl_xor_sync(0xffffffffu, p, 8);
            p += __shfl_xor_sync(0xffffffffu, p, 4);
            p += __shfl_xor_sync(0xffffffffu, p, 2);
            p += __shfl_xor_sync(0xffffffffu, p, 1);
            if (n == 0)
                g_y[(size_t)(base + s4*4 + q)*DI + d] = p + uu[q]*Dv;
        }
    }
}

// ---------------- LN over channels of out_res ----------------
__device__ __forceinline__ float bsum128(float v, float* sh){
    #pragma unroll
    for (int o = 16; o; o >>= 1) v += __shfl_xor_sync(0xffffffffu, v, o);
    __syncthreads();
    if ((threadIdx.x & 31) == 0) sh[threadIdx.x >> 5] = v;
    __syncthreads();
    return sh[0] + sh[1] + sh[2] + sh[3];
}
__global__ void k_ln_res(const float* __restrict__ lnw, const float* __restrict__ lnb){
    __shared__ float sh[4];
    int s = blockIdx.x, c = threadIdx.x;
    float v   = g_resT[(size_t)s*CCH + c];
    float m   = bsum128(v, sh) * (1.f/128.f);
    float d   = v - m;
    float var = bsum128(d*d, sh) * (1.f/128.f);
    g_tok[(size_t)s*CCH + c] = d * rsqrtf(var + 1e-6f) * lnw[c] + lnb[c];
}

// ---------------- launch ----------------
extern "C" void kernel_launch(void* const* d_in, const int* in_sizes, int n_in,
                              void* d_out, int out_size){
    const float* x        = (const float*)d_in[0];
    const float* ln_w     = (const float*)d_in[1];
    const float* ln_b     = (const float*)d_in[2];
    const float* mnorm_w  = (const float*)d_in[3];
    const float* mnorm_b  = (const float*)d_in[4];
    const float* in_proj  = (const float*)d_in[5];
    const float* conv_w   = (const float*)d_in[6];
    const float* conv_b   = (const float*)d_in[7];
    const float* x_proj   = (const float*)d_in[8];
    const float* dt_proj  = (const float*)d_in[9];
    const float* dt_bias  = (const float*)d_in[10];
    const float* A_log    = (const float*)d_in[11];
    const float* D_param  = (const float*)d_in[12];
    const float* out_proj = (const float*)d_in[13];
    const float* proj_w   = (const float*)d_in[14];
    const float* proj_b   = (const float*)d_in[15];
    const float* fc1_w    = (const float*)d_in[16];
    const float* fc1_b    = (const float*)d_in[17];
    const float* fc2_w    = (const float*)d_in[18];
    const float* fc2_b    = (const float*)d_in[19];
    float* out = (float*)d_out;

    void *p_tok, *p_xz, *p_xc, *p_part, *p_y, *p_mo, *p_resT, *p_hid, *p_xT;
    cudaGetSymbolAddress(&p_tok,  g_tok);
    cudaGetSymbolAddress(&p_xz,   g_xz);
    cudaGetSymbolAddress(&p_xc,   g_xc);
    cudaGetSymbolAddress(&p_part, g_part);
    cudaGetSymbolAddress(&p_y,    g_y);
    cudaGetSymbolAddress(&p_mo,   g_mo);
    cudaGetSymbolAddress(&p_resT, g_resT);
    cudaGetSymbolAddress(&p_hid,  g_hid);
    cudaGetSymbolAddress(&p_xT,   g_xT);

    // 1. fused transpose + double token LN
    k_lnx<<<L/32, 256>>>(x, ln_w, ln_b, mnorm_w, mnorm_b);
    // 2. in_proj: [4096,128]@[512,128]^T
    k_tgemm<128,0,false,false,false,0,false><<<dim3(L/128, 8), 256>>>(
        (const float*)p_tok, in_proj, nullptr, nullptr, (float*)p_xz, 512, 128, nullptr);
    // 3. conv + silu, dual-layout store
    k_conv<<<dim3(L/CTL, NDIR), DI>>>(conv_w, conv_b);
    // 4. x_dbl split-K GEMM -> partials
    k_tgemm<64,0,false,false,false,0,true><<<dim3(LT/64, 1, 4), 256>>>(
        (const float*)p_xc, x_proj, nullptr, nullptr, (float*)p_part, 40, 256, nullptr);
    // 5. fixup: sum parts, delta, transposed B/C/delta
    k_fixup<<<LT/64, 256>>>(dt_proj, dt_bias);
    // 6. fused selective scan
    k_scan<<<NDIR*DI, 1024>>>(A_log, D_param);
    // 7. out_proj with fused silu(z) gating in A-load
    k_tgemm<64,0,false,false,false,2,false><<<dim3(LT/64, 2), 256>>>(
        (const float*)p_y, out_proj, nullptr, nullptr, (float*)p_mo, 128, 256, (const float*)p_xz);
    // 8. proj(384->128) with fused 3-dir gather + bias + x residual
    k_tgemm<32,0,true,true,false,1,false><<<dim3(L/32, 2), 256>>>(
        (const float*)p_mo, proj_w, proj_b, (const float*)p_xT, (float*)p_resT, 128, 384, nullptr);
    // 9. LN(out_res)
    k_ln_res<<<L, 128>>>(ln_w, ln_b);
    // 10. fc1 + exact GELU
    k_tgemm<128,2,true,false,false,0,false><<<dim3(L/128, 8), 256>>>(
        (const float*)p_tok, fc1_w, fc1_b, nullptr, (float*)p_hid, 512, 128, nullptr);
    // 11. fc2 + bias + residual + transposed store to (C,D,H,W)
    k_tgemm<32,0,true,true,true,0,false><<<dim3(L/32, 2), 256>>>(
        (const float*)p_hid, fc2_w, fc2_b, (const float*)p_resT, out, 128, 512, nullptr);
}

// round 5
// speedup vs baseline: 1.1748x; 1.1748x over previous
#include <cuda_runtime.h>
#include <math.h>

#define L     4096
#define CCH   128
#define DI    256
#define NDIR  3
#define LT    (NDIR*L)
#define DS    16
#define NCHUNK 64
#define CHLEN  64
#define CTL   16

// ---------------- scratch ----------------
__device__ float g_xT[L*CCH];
__device__ float g_tok[L*CCH];
__device__ float g_xz[L*2*DI];
__device__ float g_xcT[DI*LT];        // conv+silu, [d][lg]
__device__ float g_zT[DI*LT];         // silu(z) gathered, [d][lg]
__device__ float g_BCT[32*LT];        // rows 0..15 B^T, 16..31 C^T, [n][lg]
__device__ float g_deltaT[DI*LT];     // [d][lg]
__device__ float g_yT[DI*LT];         // gated scan output, [d][lg]
__device__ float g_mo[LT*CCH];
__device__ float g_resT[L*CCH];
__device__ float g_hid[L*512];

typedef unsigned long long u64;

__device__ __forceinline__ void ffma2(u64 &d, u64 a, u64 b){
    asm("fma.rn.f32x2 %0, %1, %2, %0;" : "+l"(d) : "l"(a), "l"(b));
}
__device__ __forceinline__ u64 packdup(float v){
    u64 r; asm("mov.b64 %0, {%1, %1};" : "=l"(r) : "f"(v)); return r;
}
__device__ __forceinline__ void unpack2(u64 v, float &lo, float &hi){
    asm("mov.b64 {%0, %1}, %2;" : "=f"(lo), "=f"(hi) : "l"(v));
}

__device__ __forceinline__ int ptok(int dir, int l){
    int a = l >> 8, b = (l >> 4) & 15, c = l & 15;
    if (dir == 0) return l;
    if (dir == 1) return c*256 + a*16 + b;
    return b*256 + c*16 + a;
}
__device__ __forceinline__ int stol(int dir, int s){
    int a = s >> 8, b = (s >> 4) & 15, cc = s & 15;
    if (dir == 0) return s;
    if (dir == 1) return b*256 + cc*16 + a;
    return cc*256 + a*16 + b;
}

// ---------------- K1: fused transpose + double LayerNorm ----------------
__global__ void k_lnx(const float* __restrict__ x,
                      const float* __restrict__ lnw, const float* __restrict__ lnb,
                      const float* __restrict__ mw,  const float* __restrict__ mb){
    __shared__ float t[128][33];
    int s0 = blockIdx.x*32;
    int lane = threadIdx.x & 31, w = threadIdx.x >> 5;
    for (int r = w; r < 128; r += 8)
        t[r][lane] = x[(size_t)r*L + s0 + lane];
    __syncthreads();
    for (int round = 0; round < 4; round++){
        int tloc = round*8 + w;
        int s = s0 + tloc;
        float v[4];
        #pragma unroll
        for (int i = 0; i < 4; i++) v[i] = t[lane + 32*i][tloc];
        #pragma unroll
        for (int i = 0; i < 4; i++) g_xT[(size_t)s*CCH + lane + 32*i] = v[i];
        float sum = v[0]+v[1]+v[2]+v[3];
        #pragma unroll
        for (int o = 16; o; o >>= 1) sum += __shfl_xor_sync(0xffffffffu, sum, o);
        float mean = sum * (1.f/128.f);
        float d[4], var = 0.f;
        #pragma unroll
        for (int i = 0; i < 4; i++){ d[i] = v[i]-mean; var += d[i]*d[i]; }
        #pragma unroll
        for (int o = 16; o; o >>= 1) var += __shfl_xor_sync(0xffffffffu, var, o);
        float rs = rsqrtf(var*(1.f/128.f) + 1e-6f);
        float v1[4];
        #pragma unroll
        for (int i = 0; i < 4; i++){
            int c = lane + 32*i;
            v1[i] = d[i]*rs*lnw[c] + lnb[c];
        }
        float sum2 = v1[0]+v1[1]+v1[2]+v1[3];
        #pragma unroll
        for (int o = 16; o; o >>= 1) sum2 += __shfl_xor_sync(0xffffffffu, sum2, o);
        float mean2 = sum2 * (1.f/128.f);
        float d2[4], var2 = 0.f;
        #pragma unroll
        for (int i = 0; i < 4; i++){ d2[i] = v1[i]-mean2; var2 += d2[i]*d2[i]; }
        #pragma unroll
        for (int o = 16; o; o >>= 1) var2 += __shfl_xor_sync(0xffffffffu, var2, o);
        float rs2 = rsqrtf(var2*(1.f/128.f) + 1e-5f);
        #pragma unroll
        for (int i = 0; i < 4; i++){
            int c = lane + 32*i;
            g_tok[(size_t)s*CCH + c] = d2[i]*rs2*mw[c] + mb[c];
        }
    }
}

// ---------------- f32x2 tiled SGEMM (R3-proven inner loop, KS templated) ----------------
// AMODE: 0 row-major A[m][k]; 1 PERM gather (A = g_mo, 3-dir); 3 transposed A[k][m] (k-major, LT stride)
// XDBL: special epilogue -> g_BCT + g_deltaT (requires TM=32, N=40)
template<int TM, int KS, int ACT, bool BIAS, bool RES, bool TSTORE, int AMODE, bool XDBL>
__global__ void __launch_bounds__(256) k_tgemm(
                        const float* __restrict__ A,
                        const float* __restrict__ W,
                        const float* __restrict__ bias,
                        const float* __restrict__ res,
                        float* __restrict__ out,
                        int N, int K,
                        const float* __restrict__ dtw,
                        const float* __restrict__ dtb){
    constexpr int TN = 64;
    constexpr int NP = TM/32;
    constexpr int ALN = TM*KS/1024;     // float4 A loads per thread
    constexpr int BLN = KS/16;          // float4 B loads per thread
    __shared__ __align__(16) float As[KS][TM+4];
    __shared__ __align__(16) float Bs[KS][TN+4];
    __shared__ float sout[XDBL ? 32 : 1][XDBL ? 44 : 1];
    __shared__ float sdel[XDBL ? 16 : 1][XDBL ? 260 : 1];
    int tid = threadIdx.x;
    int tx = tid & 15, ty = tid >> 4;
    int m0 = blockIdx.x * TM, n0 = blockIdx.y * TN;

    u64 acc[NP][4];
    #pragma unroll
    for (int p = 0; p < NP; p++)
        #pragma unroll
        for (int j = 0; j < 4; j++) acc[p][j] = 0ull;

    float4 ra[ALN]; float4 rb[BLN];
    auto loadTile = [&](int k0){
        #pragma unroll
        for (int i = 0; i < ALN; i++){
            int idx = tid + i*256;
            if (AMODE == 3){
                int kk = idx / (TM/4), mq = idx % (TM/4);
                ra[i] = *(const float4*)(A + (size_t)(k0+kk)*LT + m0 + mq*4);
            } else {
                int m = idx / (KS/4), kq = idx % (KS/4);
                int k = k0 + kq*4;
                if (AMODE == 1){
                    int dir = k >> 7, c = k & 127;
                    int l = stol(dir, m0 + m);
                    ra[i] = *(const float4*)(A + ((size_t)(dir*L + l)*CCH + c));
                } else {
                    ra[i] = *(const float4*)(A + (size_t)(m0+m)*K + k);
                }
            }
        }
        #pragma unroll
        for (int i = 0; i < BLN; i++){
            int idx = tid + i*256;
            int n = idx / (KS/4), kq = idx % (KS/4);
            rb[i] = make_float4(0.f,0.f,0.f,0.f);
            if (n0 + n < N)
                rb[i] = *(const float4*)(W + (size_t)(n0+n)*K + k0 + kq*4);
        }
    };
    auto storeTile = [&](){
        #pragma unroll
        for (int i = 0; i < ALN; i++){
            int idx = tid + i*256;
            if (AMODE == 3){
                int kk = idx / (TM/4), mq = idx % (TM/4);
                *(float4*)&As[kk][mq*4] = ra[i];
            } else {
                int m = idx / (KS/4), kq = idx % (KS/4);
                As[kq*4+0][m] = ra[i].x; As[kq*4+1][m] = ra[i].y;
                As[kq*4+2][m] = ra[i].z; As[kq*4+3][m] = ra[i].w;
            }
        }
        #pragma unroll
        for (int i = 0; i < BLN; i++){
            int idx = tid + i*256;
            int n = idx / (KS/4), kq = idx % (KS/4);
            Bs[kq*4+0][n] = rb[i].x; Bs[kq*4+1][n] = rb[i].y;
            Bs[kq*4+2][n] = rb[i].z; Bs[kq*4+3][n] = rb[i].w;
        }
    };

    int NT = K / KS;
    loadTile(0);
    for (int t = 0; t < NT; t++){
        storeTile();
        __syncthreads();
        if (t + 1 < NT) loadTile((t+1)*KS);
        #pragma unroll
        for (int kk = 0; kk < KS; kk++){
            float4 bv = *(const float4*)&Bs[kk][tx*4];
            u64 bd[4];
            bd[0] = packdup(bv.x); bd[1] = packdup(bv.y);
            bd[2] = packdup(bv.z); bd[3] = packdup(bv.w);
            u64 ap[NP];
            if (TM == 32){
                ap[0] = *(const u64*)&As[kk][ty*2];
            } else if (TM == 64){
                const u64* p = (const u64*)&As[kk][ty*4];
                ap[0] = p[0]; ap[1] = p[1];
            } else {
                const u64* p0 = (const u64*)&As[kk][ty*4];
                const u64* p1 = (const u64*)&As[kk][64 + ty*4];
                ap[0] = p0[0]; ap[1] = p0[1]; ap[2] = p1[0]; ap[3] = p1[1];
            }
            #pragma unroll
            for (int p = 0; p < NP; p++)
                #pragma unroll
                for (int j = 0; j < 4; j++)
                    ffma2(acc[p][j], ap[p], bd[j]);
        }
        __syncthreads();
    }

    #pragma unroll
    for (int p = 0; p < NP; p++){
        int rbase = (TM == 32) ? ty*2
                  : (TM == 64) ? ty*4 + p*2
                  : (p >> 1)*64 + ty*4 + (p & 1)*2;
        #pragma unroll
        for (int j = 0; j < 4; j++){
            int n = n0 + tx*4 + j;
            if (n >= N) continue;
            float lo, hi;
            unpack2(acc[p][j], lo, hi);
            #pragma unroll
            for (int half = 0; half < 2; half++){
                int m = m0 + rbase + half;
                float v = half ? hi : lo;
                if (XDBL){
                    sout[rbase + half][n] = v;
                    continue;
                }
                if (BIAS) v += bias[n];
                if (ACT == 1)      v = v / (1.f + __expf(-v));
                else if (ACT == 2) v = 0.5f * v * (1.f + erff(v * 0.70710678118654752f));
                if (RES) v += res[(size_t)m*N + n];
                if (TSTORE) out[(size_t)n*L + m] = v;
                else        out[(size_t)m*N + n] = v;
            }
        }
    }

    if (XDBL){
        __syncthreads();
        // B^T / C^T: cols 8..39 of sout -> g_BCT[n][m0..m0+31]
        {
            int n = tid >> 3, mq = tid & 7;      // n 0..31, mq 0..7
            float4 v;
            v.x = sout[mq*4+0][8+n]; v.y = sout[mq*4+1][8+n];
            v.z = sout[mq*4+2][8+n]; v.w = sout[mq*4+3][8+n];
            *(float4*)&g_BCT[(size_t)n*LT + m0 + mq*4] = v;
        }
        // delta^T in two halves of 16 rows
        float wr[8];
        #pragma unroll
        for (int r = 0; r < 8; r++) wr[r] = dtw[tid*8 + r];
        float bb = dtb[tid];
        #pragma unroll
        for (int hf = 0; hf < 2; hf++){
            __syncthreads();
            for (int r = 0; r < 16; r++){
                int row = hf*16 + r;
                float a = bb;
                #pragma unroll
                for (int q = 0; q < 8; q++) a = fmaf(wr[q], sout[row][q], a);
                a = (a > 20.f) ? a : log1pf(__expf(a));
                sdel[r][tid] = a;
            }
            __syncthreads();
            int mq = tid & 3, db = tid >> 2;     // db 0..63
            #pragma unroll
            for (int it = 0; it < 4; it++){
                int d = db + 64*it;
                float4 v;
                v.x = sdel[mq*4+0][d]; v.y = sdel[mq*4+1][d];
                v.z = sdel[mq*4+2][d]; v.w = sdel[mq*4+3][d];
                *(float4*)&g_deltaT[(size_t)d*LT + m0 + hf*16 + mq*4] = v;
            }
        }
    }
}

// ---------------- conv: causal depthwise k=4 + silu -> xcT; silu(z) -> zT ----------------
__global__ void k_conv(const float* __restrict__ cw, const float* __restrict__ cb){
    __shared__ float sx[CTL+3][DI];
    __shared__ float sy[CTL][260];
    int dir = blockIdx.y, l0 = blockIdx.x*CTL, ch = threadIdx.x;
    for (int r = 0; r < CTL+3; r++){
        int row = l0 - 3 + r;
        sx[r][ch] = (row >= 0) ? g_xz[(size_t)ptok(dir, row)*(2*DI) + ch] : 0.f;
    }
    __syncthreads();
    float w0 = cw[ch*4+0], w1 = cw[ch*4+1], w2 = cw[ch*4+2], w3 = cw[ch*4+3];
    float b = cb[ch];
    for (int i = 0; i < CTL; i++){
        float acc = b + w0*sx[i][ch] + w1*sx[i+1][ch] + w2*sx[i+2][ch] + w3*sx[i+3][ch];
        acc = acc / (1.f + __expf(-acc));
        sy[i][ch] = acc;
    }
    __syncthreads();
    int mq = threadIdx.x & 3, chb = threadIdx.x >> 2;
    #pragma unroll
    for (int it = 0; it < 4; it++){
        int c2 = chb + 64*it;
        float4 v;
        v.x = sy[mq*4+0][c2]; v.y = sy[mq*4+1][c2];
        v.z = sy[mq*4+2][c2]; v.w = sy[mq*4+3][c2];
        *(float4*)&g_xcT[(size_t)c2*LT + dir*L + l0 + mq*4] = v;
    }
    __syncthreads();
    // phase 2: z half, silu, transposed store
    for (int i = 0; i < CTL; i++){
        float z = g_xz[(size_t)ptok(dir, l0 + i)*(2*DI) + DI + ch];
        sy[i][ch] = z / (1.f + __expf(-z));
    }
    __syncthreads();
    #pragma unroll
    for (int it = 0; it < 4; it++){
        int c2 = chb + 64*it;
        float4 v;
        v.x = sy[mq*4+0][c2]; v.y = sy[mq*4+1][c2];
        v.z = sy[mq*4+2][c2]; v.w = sy[mq*4+3][c2];
        *(float4*)&g_zT[(size_t)c2*LT + dir*L + l0 + mq*4] = v;
    }
}

// ---------------- fused selective scan (float4 streams, gated coalesced output) ----------------
__global__ void __launch_bounds__(1024) k_scan(const float* __restrict__ Alog,
                                               const float* __restrict__ Dp){
    __shared__ float sP[NCHUNK][DS];
    __shared__ float sS[NCHUNK][DS];
    __shared__ float sY[L];
    int bx = blockIdx.x;
    int dir = bx >> 8, d = bx & 255;
    int tid = threadIdx.x;
    int chunk = tid >> 4, n = tid & 15;
    float Av = -__expf(Alog[d*DS + n]);
    int base = dir*L + chunk*CHLEN;
    const float* dptr = g_deltaT + (size_t)d*LT + base;
    const float* uptr = g_xcT   + (size_t)d*LT + base;
    const float* bptr = g_BCT   + (size_t)n*LT + base;
    const float* cptr = g_BCT   + (size_t)(16+n)*LT + base;

    // pass A: chunk summaries
    float P = 1.f, S = 0.f;
    for (int s4 = 0; s4 < CHLEN/4; s4++){
        float4 dl4 = *(const float4*)(dptr + s4*4);
        float4 u4  = *(const float4*)(uptr + s4*4);
        float4 B4  = *(const float4*)(bptr + s4*4);
        const float* dl = &dl4.x; const float* uu = &u4.x; const float* BB = &B4.x;
        #pragma unroll
        for (int q = 0; q < 4; q++){
            float a = __expf(dl[q] * Av);
            P *= a;
            S = a*S + dl[q]*BB[q]*uu[q];
        }
    }
    sP[chunk][n] = P; sS[chunk][n] = S;
    __syncthreads();

    // Kogge-Stone inclusive scan over chunks
    #pragma unroll
    for (int off = 1; off < NCHUNK; off <<= 1){
        float pP = 1.f, pS = 0.f;
        if (chunk >= off){ pP = sP[chunk-off][n]; pS = sS[chunk-off][n]; }
        __syncthreads();
        S = fmaf(P, pS, S);
        P *= pP;
        sP[chunk][n] = P; sS[chunk][n] = S;
        __syncthreads();
    }
    float h = (chunk > 0) ? sS[chunk-1][n] : 0.f;

    // pass C
    float Dv = Dp[d];
    for (int s4 = 0; s4 < CHLEN/4; s4++){
        float4 dl4 = *(const float4*)(dptr + s4*4);
        float4 u4  = *(const float4*)(uptr + s4*4);
        float4 B4  = *(const float4*)(bptr + s4*4);
        float4 C4  = *(const float4*)(cptr + s4*4);
        const float* dl = &dl4.x; const float* uu = &u4.x;
        const float* BB = &B4.x;  const float* CC = &C4.x;
        #pragma unroll
        for (int q = 0; q < 4; q++){
            float a = __expf(dl[q] * Av);
            h = a*h + dl[q]*BB[q]*uu[q];
            float p = h * CC[q];
            p += __shfl_xor_sync(0xffffffffu, p, 8);
            p += __shfl_xor_sync(0xffffffffu, p, 4);
            p += __shfl_xor_sync(0xffffffffu, p, 2);
            p += __shfl_xor_sync(0xffffffffu, p, 1);
            if (n == 0) sY[chunk*CHLEN + s4*4 + q] = p + uu[q]*Dv;
        }
    }
    __syncthreads();
    // gated coalesced store: y = sY * silu(z)
    {
        float4 y = *(const float4*)&sY[tid*4];
        float4 z = *(const float4*)(g_zT + (size_t)d*LT + dir*L + tid*4);
        y.x *= z.x; y.y *= z.y; y.z *= z.z; y.w *= z.w;
        *(float4*)(g_yT + (size_t)d*LT + dir*L + tid*4) = y;
    }
}

// ---------------- LN over channels of out_res ----------------
__device__ __forceinline__ float bsum128(float v, float* sh){
    #pragma unroll
    for (int o = 16; o; o >>= 1) v += __shfl_xor_sync(0xffffffffu, v, o);
    __syncthreads();
    if ((threadIdx.x & 31) == 0) sh[threadIdx.x >> 5] = v;
    __syncthreads();
    return sh[0] + sh[1] + sh[2] + sh[3];
}
__global__ void k_ln_res(const float* __restrict__ lnw, const float* __restrict__ lnb){
    __shared__ float sh[4];
    int s = blockIdx.x, c = threadIdx.x;
    float v   = g_resT[(size_t)s*CCH + c];
    float m   = bsum128(v, sh) * (1.f/128.f);
    float d   = v - m;
    float var = bsum128(d*d, sh) * (1.f/128.f);
    g_tok[(size_t)s*CCH + c] = d * rsqrtf(var + 1e-6f) * lnw[c] + lnb[c];
}

// ---------------- launch ----------------
extern "C" void kernel_launch(void* const* d_in, const int* in_sizes, int n_in,
                              void* d_out, int out_size){
    const float* x        = (const float*)d_in[0];
    const float* ln_w     = (const float*)d_in[1];
    const float* ln_b     = (const float*)d_in[2];
    const float* mnorm_w  = (const float*)d_in[3];
    const float* mnorm_b  = (const float*)d_in[4];
    const float* in_proj  = (const float*)d_in[5];
    const float* conv_w   = (const float*)d_in[6];
    const float* conv_b   = (const float*)d_in[7];
    const float* x_proj   = (const float*)d_in[8];
    const float* dt_proj  = (const float*)d_in[9];
    const float* dt_bias  = (const float*)d_in[10];
    const float* A_log    = (const float*)d_in[11];
    const float* D_param  = (const float*)d_in[12];
    const float* out_proj = (const float*)d_in[13];
    const float* proj_w   = (const float*)d_in[14];
    const float* proj_b   = (const float*)d_in[15];
    const float* fc1_w    = (const float*)d_in[16];
    const float* fc1_b    = (const float*)d_in[17];
    const float* fc2_w    = (const float*)d_in[18];
    const float* fc2_b    = (const float*)d_in[19];
    float* out = (float*)d_out;

    void *p_tok, *p_xz, *p_xcT, *p_yT, *p_mo, *p_resT, *p_hid, *p_xT, *p_bct;
    cudaGetSymbolAddress(&p_tok,  g_tok);
    cudaGetSymbolAddress(&p_xz,   g_xz);
    cudaGetSymbolAddress(&p_xcT,  g_xcT);
    cudaGetSymbolAddress(&p_yT,   g_yT);
    cudaGetSymbolAddress(&p_mo,   g_mo);
    cudaGetSymbolAddress(&p_resT, g_resT);
    cudaGetSymbolAddress(&p_hid,  g_hid);
    cudaGetSymbolAddress(&p_xT,   g_xT);
    cudaGetSymbolAddress(&p_bct,  g_BCT);

    // 1. fused transpose + double token LN
    k_lnx<<<L/32, 256>>>(x, ln_w, ln_b, mnorm_w, mnorm_b);
    // 2. in_proj: [4096,128]@[512,128]^T
    k_tgemm<128,32,0,false,false,false,0,false><<<dim3(L/128, 8), 256>>>(
        (const float*)p_tok, in_proj, nullptr, nullptr, (float*)p_xz, 512, 128, nullptr, nullptr);
    // 3. conv + silu -> xcT ; silu(z) -> zT
    k_conv<<<dim3(L/CTL, NDIR), DI>>>(conv_w, conv_b);
    // 4. x_dbl GEMM (transposed A from xcT) + epilogue -> BCT, deltaT
    k_tgemm<32,32,0,false,false,false,3,true><<<dim3(LT/32, 1), 256>>>(
        (const float*)p_xcT, x_proj, nullptr, nullptr, (float*)p_bct, 40, 256, dt_proj, dt_bias);
    // 5. fused selective scan (gated, coalesced) -> yT
    k_scan<<<NDIR*DI, 1024>>>(A_log, D_param);
    // 6. out_proj: transposed A from yT
    k_tgemm<64,32,0,false,false,false,3,false><<<dim3(LT/64, 2), 256>>>(
        (const float*)p_yT, out_proj, nullptr, nullptr, (float*)p_mo, 128, 256, nullptr, nullptr);
    // 7. proj(384->128) with fused 3-dir gather + bias + x residual
    k_tgemm<32,32,0,true,true,false,1,false><<<dim3(L/32, 2), 256>>>(
        (const float*)p_mo, proj_w, proj_b, (const float*)p_xT, (float*)p_resT, 128, 384, nullptr, nullptr);
    // 8. LN(out_res)
    k_ln_res<<<L, 128>>>(ln_w, ln_b);
    // 9. fc1 + exact GELU
    k_tgemm<128,32,2,true,false,false,0,false><<<dim3(L/128, 8), 256>>>(
        (const float*)p_tok, fc1_w, fc1_b, nullptr, (float*)p_hid, 512, 128, nullptr, nullptr);
    // 10. fc2 + bias + residual + transposed store to (C,D,H,W)
    k_tgemm<32,32,0,true,true,true,0,false><<<dim3(L/32, 2), 256>>>(
        (const float*)p_hid, fc2_w, fc2_b, (const float*)p_resT, out, 128, 512, nullptr, nullptr);
}

// round 6
// speedup vs baseline: 1.1783x; 1.0029x over previous
#include <cuda_runtime.h>
#include <math.h>

#define L     4096
#define CCH   128
#define DI    256
#define NDIR  3
#define LT    (NDIR*L)
#define DS    16
#define NCHUNK 64
#define CHLEN  64
#define CTL   16

// ---------------- scratch ----------------
__device__ float g_xT[L*CCH];
__device__ float g_tok[L*CCH];
__device__ float g_xz[L*2*DI];
__device__ float g_xcT[DI*LT];        // conv+silu, [d][lg]
__device__ float g_zT[DI*LT];         // silu(z) gathered, [d][lg]
__device__ float g_BCT[32*LT];        // rows 0..15 B^T, 16..31 C^T, [n][lg]
__device__ float g_deltaT[DI*LT];     // [d][lg]
__device__ float g_yT[DI*LT];         // gated scan output, [d][lg]
__device__ float g_mo[LT*CCH];
__device__ float g_resT[L*CCH];
__device__ float g_hid[L*512];

typedef unsigned long long u64;

__device__ __forceinline__ void ffma2(u64 &d, u64 a, u64 b){
    asm("fma.rn.f32x2 %0, %1, %2, %0;" : "+l"(d) : "l"(a), "l"(b));
}
__device__ __forceinline__ u64 packdup(float v){
    u64 r; asm("mov.b64 %0, {%1, %1};" : "=l"(r) : "f"(v)); return r;
}
__device__ __forceinline__ void unpack2(u64 v, float &lo, float &hi){
    asm("mov.b64 {%0, %1}, %2;" : "=f"(lo), "=f"(hi) : "l"(v));
}

__device__ __forceinline__ int ptok(int dir, int l){
    int a = l >> 8, b = (l >> 4) & 15, c = l & 15;
    if (dir == 0) return l;
    if (dir == 1) return c*256 + a*16 + b;
    return b*256 + c*16 + a;
}
__device__ __forceinline__ int stol(int dir, int s){
    int a = s >> 8, b = (s >> 4) & 15, cc = s & 15;
    if (dir == 0) return s;
    if (dir == 1) return b*256 + cc*16 + a;
    return cc*256 + a*16 + b;
}

// ---------------- K1: fused transpose + double LayerNorm ----------------
__global__ void k_lnx(const float* __restrict__ x,
                      const float* __restrict__ lnw, const float* __restrict__ lnb,
                      const float* __restrict__ mw,  const float* __restrict__ mb){
    __shared__ float t[128][33];
    int s0 = blockIdx.x*32;
    int lane = threadIdx.x & 31, w = threadIdx.x >> 5;
    for (int r = w; r < 128; r += 8)
        t[r][lane] = x[(size_t)r*L + s0 + lane];
    __syncthreads();
    for (int round = 0; round < 4; round++){
        int tloc = round*8 + w;
        int s = s0 + tloc;
        float v[4];
        #pragma unroll
        for (int i = 0; i < 4; i++) v[i] = t[lane + 32*i][tloc];
        #pragma unroll
        for (int i = 0; i < 4; i++) g_xT[(size_t)s*CCH + lane + 32*i] = v[i];
        float sum = v[0]+v[1]+v[2]+v[3];
        #pragma unroll
        for (int o = 16; o; o >>= 1) sum += __shfl_xor_sync(0xffffffffu, sum, o);
        float mean = sum * (1.f/128.f);
        float d[4], var = 0.f;
        #pragma unroll
        for (int i = 0; i < 4; i++){ d[i] = v[i]-mean; var += d[i]*d[i]; }
        #pragma unroll
        for (int o = 16; o; o >>= 1) var += __shfl_xor_sync(0xffffffffu, var, o);
        float rs = rsqrtf(var*(1.f/128.f) + 1e-6f);
        float v1[4];
        #pragma unroll
        for (int i = 0; i < 4; i++){
            int c = lane + 32*i;
            v1[i] = d[i]*rs*lnw[c] + lnb[c];
        }
        float sum2 = v1[0]+v1[1]+v1[2]+v1[3];
        #pragma unroll
        for (int o = 16; o; o >>= 1) sum2 += __shfl_xor_sync(0xffffffffu, sum2, o);
        float mean2 = sum2 * (1.f/128.f);
        float d2[4], var2 = 0.f;
        #pragma unroll
        for (int i = 0; i < 4; i++){ d2[i] = v1[i]-mean2; var2 += d2[i]*d2[i]; }
        #pragma unroll
        for (int o = 16; o; o >>= 1) var2 += __shfl_xor_sync(0xffffffffu, var2, o);
        float rs2 = rsqrtf(var2*(1.f/128.f) + 1e-5f);
        #pragma unroll
        for (int i = 0; i < 4; i++){
            int c = lane + 32*i;
            g_tok[(size_t)s*CCH + c] = d2[i]*rs2*mw[c] + mb[c];
        }
    }
}

// ---------------- f32x2 tiled SGEMM (R3 inner loop, KS=16) ----------------
// AMODE: 0 row-major A[m][k]; 1 PERM gather (A = g_mo, 3-dir); 3 transposed A[k][m] (LT stride)
// XDBL: epilogue -> g_BCT + g_deltaT (requires TM=32, N=40)
template<int TM, int KS, int ACT, bool BIAS, bool RES, bool TSTORE, int AMODE, bool XDBL>
__global__ void __launch_bounds__(256) k_tgemm(
                        const float* __restrict__ A,
                        const float* __restrict__ W,
                        const float* __restrict__ bias,
                        const float* __restrict__ res,
                        float* __restrict__ out,
                        int N, int K,
                        const float* __restrict__ dtw,
                        const float* __restrict__ dtb){
    constexpr int TN = 64;
    constexpr int NP = TM/32;
    constexpr int ATOT = TM*KS/4;                 // total float4 A loads
    constexpr int ALN = (ATOT + 255)/256;
    constexpr int BLN = TN*KS/4/256;              // 1 for KS=16
    __shared__ __align__(16) float As[KS][TM+4];
    __shared__ __align__(16) float Bs[KS][TN+4];
    __shared__ float sout[XDBL ? 32 : 1][XDBL ? 44 : 1];
    __shared__ float sdel[XDBL ? 16 : 1][XDBL ? 260 : 1];
    int tid = threadIdx.x;
    int tx = tid & 15, ty = tid >> 4;
    int m0 = blockIdx.x * TM, n0 = blockIdx.y * TN;

    u64 acc[NP][4];
    #pragma unroll
    for (int p = 0; p < NP; p++)
        #pragma unroll
        for (int j = 0; j < 4; j++) acc[p][j] = 0ull;

    float4 ra[ALN]; float4 rb[BLN];
    auto loadTile = [&](int k0){
        #pragma unroll
        for (int i = 0; i < ALN; i++){
            int idx = tid + i*256;
            if (idx < ATOT){
                if (AMODE == 3){
                    int kk = idx / (TM/4), mq = idx % (TM/4);
                    ra[i] = *(const float4*)(A + (size_t)(k0+kk)*LT + m0 + mq*4);
                } else {
                    int m = idx / (KS/4), kq = idx % (KS/4);
                    int k = k0 + kq*4;
                    if (AMODE == 1){
                        int dir = k >> 7, c = k & 127;
                        int l = stol(dir, m0 + m);
                        ra[i] = *(const float4*)(A + ((size_t)(dir*L + l)*CCH + c));
                    } else {
                        ra[i] = *(const float4*)(A + (size_t)(m0+m)*K + k);
                    }
                }
            }
        }
        #pragma unroll
        for (int i = 0; i < BLN; i++){
            int idx = tid + i*256;
            int n = idx / (KS/4), kq = idx % (KS/4);
            rb[i] = make_float4(0.f,0.f,0.f,0.f);
            if (n0 + n < N)
                rb[i] = *(const float4*)(W + (size_t)(n0+n)*K + k0 + kq*4);
        }
    };
    auto storeTile = [&](){
        #pragma unroll
        for (int i = 0; i < ALN; i++){
            int idx = tid + i*256;
            if (idx < ATOT){
                if (AMODE == 3){
                    int kk = idx / (TM/4), mq = idx % (TM/4);
                    *(float4*)&As[kk][mq*4] = ra[i];
                } else {
                    int m = idx / (KS/4), kq = idx % (KS/4);
                    As[kq*4+0][m] = ra[i].x; As[kq*4+1][m] = ra[i].y;
                    As[kq*4+2][m] = ra[i].z; As[kq*4+3][m] = ra[i].w;
                }
            }
        }
        #pragma unroll
        for (int i = 0; i < BLN; i++){
            int idx = tid + i*256;
            int n = idx / (KS/4), kq = idx % (KS/4);
            Bs[kq*4+0][n] = rb[i].x; Bs[kq*4+1][n] = rb[i].y;
            Bs[kq*4+2][n] = rb[i].z; Bs[kq*4+3][n] = rb[i].w;
        }
    };

    int NT = K / KS;
    loadTile(0);
    for (int t = 0; t < NT; t++){
        storeTile();
        __syncthreads();
        if (t + 1 < NT) loadTile((t+1)*KS);
        #pragma unroll
        for (int kk = 0; kk < KS; kk++){
            float4 bv = *(const float4*)&Bs[kk][tx*4];
            u64 bd[4];
            bd[0] = packdup(bv.x); bd[1] = packdup(bv.y);
            bd[2] = packdup(bv.z); bd[3] = packdup(bv.w);
            u64 ap[NP];
            if (TM == 32){
                ap[0] = *(const u64*)&As[kk][ty*2];
            } else if (TM == 64){
                const u64* p = (const u64*)&As[kk][ty*4];
                ap[0] = p[0]; ap[1] = p[1];
            } else {
                const u64* p0 = (const u64*)&As[kk][ty*4];
                const u64* p1 = (const u64*)&As[kk][64 + ty*4];
                ap[0] = p0[0]; ap[1] = p0[1]; ap[2] = p1[0]; ap[3] = p1[1];
            }
            #pragma unroll
            for (int p = 0; p < NP; p++)
                #pragma unroll
                for (int j = 0; j < 4; j++)
                    ffma2(acc[p][j], ap[p], bd[j]);
        }
        __syncthreads();
    }

    #pragma unroll
    for (int p = 0; p < NP; p++){
        int rbase = (TM == 32) ? ty*2
                  : (TM == 64) ? ty*4 + p*2
                  : (p >> 1)*64 + ty*4 + (p & 1)*2;
        #pragma unroll
        for (int j = 0; j < 4; j++){
            int n = n0 + tx*4 + j;
            if (n >= N) continue;
            float lo, hi;
            unpack2(acc[p][j], lo, hi);
            #pragma unroll
            for (int half = 0; half < 2; half++){
                int m = m0 + rbase + half;
                float v = half ? hi : lo;
                if (XDBL){
                    sout[rbase + half][n] = v;
                    continue;
                }
                if (BIAS) v += bias[n];
                if (ACT == 1)      v = v / (1.f + __expf(-v));
                else if (ACT == 2) v = 0.5f * v * (1.f + erff(v * 0.70710678118654752f));
                if (RES) v += res[(size_t)m*N + n];
                if (TSTORE) out[(size_t)n*L + m] = v;
                else        out[(size_t)m*N + n] = v;
            }
        }
    }

    if (XDBL){
        __syncthreads();
        // B^T / C^T: cols 8..39 of sout -> g_BCT[n][m0..m0+31]
        {
            int n = tid >> 3, mq = tid & 7;
            float4 v;
            v.x = sout[mq*4+0][8+n]; v.y = sout[mq*4+1][8+n];
            v.z = sout[mq*4+2][8+n]; v.w = sout[mq*4+3][8+n];
            *(float4*)&g_BCT[(size_t)n*LT + m0 + mq*4] = v;
        }
        // delta^T in two halves of 16 rows
        float wr[8];
        #pragma unroll
        for (int r = 0; r < 8; r++) wr[r] = dtw[tid*8 + r];
        float bb = dtb[tid];
        #pragma unroll
        for (int hf = 0; hf < 2; hf++){
            __syncthreads();
            for (int r = 0; r < 16; r++){
                int row = hf*16 + r;
                float a = bb;
                #pragma unroll
                for (int q = 0; q < 8; q++) a = fmaf(wr[q], sout[row][q], a);
                a = (a > 20.f) ? a : log1pf(__expf(a));
                sdel[r][tid] = a;
            }
            __syncthreads();
            int mq = tid & 3, db = tid >> 2;
            #pragma unroll
            for (int it = 0; it < 4; it++){
                int d = db + 64*it;
                float4 v;
                v.x = sdel[mq*4+0][d]; v.y = sdel[mq*4+1][d];
                v.z = sdel[mq*4+2][d]; v.w = sdel[mq*4+3][d];
                *(float4*)&g_deltaT[(size_t)d*LT + m0 + hf*16 + mq*4] = v;
            }
        }
    }
}

// ---------------- conv: causal depthwise k=4 + silu -> xcT; silu(z) -> zT ----------------
__global__ void k_conv(const float* __restrict__ cw, const float* __restrict__ cb){
    __shared__ float sx[CTL+3][DI];
    __shared__ float sy[CTL][260];
    int dir = blockIdx.y, l0 = blockIdx.x*CTL, ch = threadIdx.x;
    for (int r = 0; r < CTL+3; r++){
        int row = l0 - 3 + r;
        sx[r][ch] = (row >= 0) ? g_xz[(size_t)ptok(dir, row)*(2*DI) + ch] : 0.f;
    }
    __syncthreads();
    float w0 = cw[ch*4+0], w1 = cw[ch*4+1], w2 = cw[ch*4+2], w3 = cw[ch*4+3];
    float b = cb[ch];
    for (int i = 0; i < CTL; i++){
        float acc = b + w0*sx[i][ch] + w1*sx[i+1][ch] + w2*sx[i+2][ch] + w3*sx[i+3][ch];
        acc = acc / (1.f + __expf(-acc));
        sy[i][ch] = acc;
    }
    __syncthreads();
    int mq = threadIdx.x & 3, chb = threadIdx.x >> 2;
    #pragma unroll
    for (int it = 0; it < 4; it++){
        int c2 = chb + 64*it;
        float4 v;
        v.x = sy[mq*4+0][c2]; v.y = sy[mq*4+1][c2];
        v.z = sy[mq*4+2][c2]; v.w = sy[mq*4+3][c2];
        *(float4*)&g_xcT[(size_t)c2*LT + dir*L + l0 + mq*4] = v;
    }
    __syncthreads();
    for (int i = 0; i < CTL; i++){
        float z = g_xz[(size_t)ptok(dir, l0 + i)*(2*DI) + DI + ch];
        sy[i][ch] = z / (1.f + __expf(-z));
    }
    __syncthreads();
    #pragma unroll
    for (int it = 0; it < 4; it++){
        int c2 = chb + 64*it;
        float4 v;
        v.x = sy[mq*4+0][c2]; v.y = sy[mq*4+1][c2];
        v.z = sy[mq*4+2][c2]; v.w = sy[mq*4+3][c2];
        *(float4*)&g_zT[(size_t)c2*LT + dir*L + l0 + mq*4] = v;
    }
}

// ---------------- fused selective scan (float4 streams, gated coalesced output) ----------------
__global__ void __launch_bounds__(1024) k_scan(const float* __restrict__ Alog,
                                               const float* __restrict__ Dp){
    __shared__ float sP[NCHUNK][DS];
    __shared__ float sS[NCHUNK][DS];
    __shared__ float sY[L];
    int bx = blockIdx.x;
    int dir = bx >> 8, d = bx & 255;
    int tid = threadIdx.x;
    int chunk = tid >> 4, n = tid & 15;
    float Av = -__expf(Alog[d*DS + n]);
    int base = dir*L + chunk*CHLEN;
    const float* dptr = g_deltaT + (size_t)d*LT + base;
    const float* uptr = g_xcT   + (size_t)d*LT + base;
    const float* bptr = g_BCT   + (size_t)n*LT + base;
    const float* cptr = g_BCT   + (size_t)(16+n)*LT + base;

    float P = 1.f, S = 0.f;
    for (int s4 = 0; s4 < CHLEN/4; s4++){
        float4 dl4 = *(const float4*)(dptr + s4*4);
        float4 u4  = *(const float4*)(uptr + s4*4);
        float4 B4  = *(const float4*)(bptr + s4*4);
        const float* dl = &dl4.x; const float* uu = &u4.x; const float* BB = &B4.x;
        #pragma unroll
        for (int q = 0; q < 4; q++){
            float a = __expf(dl[q] * Av);
            P *= a;
            S = a*S + dl[q]*BB[q]*uu[q];
        }
    }
    sP[chunk][n] = P; sS[chunk][n] = S;
    __syncthreads();

    #pragma unroll
    for (int off = 1; off < NCHUNK; off <<= 1){
        float pP = 1.f, pS = 0.f;
        if (chunk >= off){ pP = sP[chunk-off][n]; pS = sS[chunk-off][n]; }
        __syncthreads();
        S = fmaf(P, pS, S);
        P *= pP;
        sP[chunk][n] = P; sS[chunk][n] = S;
        __syncthreads();
    }
    float h = (chunk > 0) ? sS[chunk-1][n] : 0.f;

    float Dv = Dp[d];
    for (int s4 = 0; s4 < CHLEN/4; s4++){
        float4 dl4 = *(const float4*)(dptr + s4*4);
        float4 u4  = *(const float4*)(uptr + s4*4);
        float4 B4  = *(const float4*)(bptr + s4*4);
        float4 C4  = *(const float4*)(cptr + s4*4);
        const float* dl = &dl4.x; const float* uu = &u4.x;
        const float* BB = &B4.x;  const float* CC = &C4.x;
        #pragma unroll
        for (int q = 0; q < 4; q++){
            float a = __expf(dl[q] * Av);
            h = a*h + dl[q]*BB[q]*uu[q];
            float p = h * CC[q];
            p += __shfl_xor_sync(0xffffffffu, p, 8);
            p += __shfl_xor_sync(0xffffffffu, p, 4);
            p += __shfl_xor_sync(0xffffffffu, p, 2);
            p += __shfl_xor_sync(0xffffffffu, p, 1);
            if (n == 0) sY[chunk*CHLEN + s4*4 + q] = p + uu[q]*Dv;
        }
    }
    __syncthreads();
    {
        float4 y = *(const float4*)&sY[tid*4];
        float4 z = *(const float4*)(g_zT + (size_t)d*LT + dir*L + tid*4);
        y.x *= z.x; y.y *= z.y; y.z *= z.z; y.w *= z.w;
        *(float4*)(g_yT + (size_t)d*LT + dir*L + tid*4) = y;
    }
}

// ---------------- LN over channels of out_res ----------------
__device__ __forceinline__ float bsum128(float v, float* sh){
    #pragma unroll
    for (int o = 16; o; o >>= 1) v += __shfl_xor_sync(0xffffffffu, v, o);
    __syncthreads();
    if ((threadIdx.x & 31) == 0) sh[threadIdx.x >> 5] = v;
    __syncthreads();
    return sh[0] + sh[1] + sh[2] + sh[3];
}
__global__ void k_ln_res(const float* __restrict__ lnw, const float* __restrict__ lnb){
    __shared__ float sh[4];
    int s = blockIdx.x, c = threadIdx.x;
    float v   = g_resT[(size_t)s*CCH + c];
    float m   = bsum128(v, sh) * (1.f/128.f);
    float d   = v - m;
    float var = bsum128(d*d, sh) * (1.f/128.f);
    g_tok[(size_t)s*CCH + c] = d * rsqrtf(var + 1e-6f) * lnw[c] + lnb[c];
}

// ---------------- launch ----------------
extern "C" void kernel_launch(void* const* d_in, const int* in_sizes, int n_in,
                              void* d_out, int out_size){
    const float* x        = (const float*)d_in[0];
    const float* ln_w     = (const float*)d_in[1];
    const float* ln_b     = (const float*)d_in[2];
    const float* mnorm_w  = (const float*)d_in[3];
    const float* mnorm_b  = (const float*)d_in[4];
    const float* in_proj  = (const float*)d_in[5];
    const float* conv_w   = (const float*)d_in[6];
    const float* conv_b   = (const float*)d_in[7];
    const float* x_proj   = (const float*)d_in[8];
    const float* dt_proj  = (const float*)d_in[9];
    const float* dt_bias  = (const float*)d_in[10];
    const float* A_log    = (const float*)d_in[11];
    const float* D_param  = (const float*)d_in[12];
    const float* out_proj = (const float*)d_in[13];
    const float* proj_w   = (const float*)d_in[14];
    const float* proj_b   = (const float*)d_in[15];
    const float* fc1_w    = (const float*)d_in[16];
    const float* fc1_b    = (const float*)d_in[17];
    const float* fc2_w    = (const float*)d_in[18];
    const float* fc2_b    = (const float*)d_in[19];
    float* out = (float*)d_out;

    void *p_tok, *p_xz, *p_xcT, *p_yT, *p_mo, *p_resT, *p_hid, *p_xT, *p_bct;
    cudaGetSymbolAddress(&p_tok,  g_tok);
    cudaGetSymbolAddress(&p_xz,   g_xz);
    cudaGetSymbolAddress(&p_xcT,  g_xcT);
    cudaGetSymbolAddress(&p_yT,   g_yT);
    cudaGetSymbolAddress(&p_mo,   g_mo);
    cudaGetSymbolAddress(&p_resT, g_resT);
    cudaGetSymbolAddress(&p_hid,  g_hid);
    cudaGetSymbolAddress(&p_xT,   g_xT);
    cudaGetSymbolAddress(&p_bct,  g_BCT);

    // 1. fused transpose + double token LN
    k_lnx<<<L/32, 256>>>(x, ln_w, ln_b, mnorm_w, mnorm_b);
    // 2. in_proj: [4096,128]@[512,128]^T
    k_tgemm<128,16,0,false,false,false,0,false><<<dim3(L/128, 8), 256>>>(
        (const float*)p_tok, in_proj, nullptr, nullptr, (float*)p_xz, 512, 128, nullptr, nullptr);
    // 3. conv + silu -> xcT ; silu(z) -> zT
    k_conv<<<dim3(L/CTL, NDIR), DI>>>(conv_w, conv_b);
    // 4. x_dbl GEMM (transposed A from xcT) + epilogue -> BCT, deltaT
    k_tgemm<32,16,0,false,false,false,3,true><<<dim3(LT/32, 1), 256>>>(
        (const float*)p_xcT, x_proj, nullptr, nullptr, (float*)p_bct, 40, 256, dt_proj, dt_bias);
    // 5. fused selective scan (gated, coalesced) -> yT
    k_scan<<<NDIR*DI, 1024>>>(A_log, D_param);
    // 6. out_proj: transposed A from yT
    k_tgemm<64,16,0,false,false,false,3,false><<<dim3(LT/64, 2), 256>>>(
        (const float*)p_yT, out_proj, nullptr, nullptr, (float*)p_mo, 128, 256, nullptr, nullptr);
    // 7. proj(384->128) with fused 3-dir gather + bias + x residual
    k_tgemm<32,16,0,true,true,false,1,false><<<dim3(L/32, 2), 256>>>(
        (const float*)p_mo, proj_w, proj_b, (const float*)p_xT, (float*)p_resT, 128, 384, nullptr, nullptr);
    // 8. LN(out_res)
    k_ln_res<<<L, 128>>>(ln_w, ln_b);
    // 9. fc1 + exact GELU
    k_tgemm<128,16,2,true,false,false,0,false><<<dim3(L/128, 8), 256>>>(
        (const float*)p_tok, fc1_w, fc1_b, nullptr, (float*)p_hid, 512, 128, nullptr, nullptr);
    // 10. fc2 + bias + residual + transposed store to (C,D,H,W)
    k_tgemm<32,16,0,true,true,true,0,false><<<dim3(L/32, 2), 256>>>(
        (const float*)p_hid, fc2_w, fc2_b, (const float*)p_resT, out, 128, 512, nullptr, nullptr);
}

// round 7
// speedup vs baseline: 1.2268x; 1.0412x over previous
#include <cuda_runtime.h>
#include <math.h>

#define L     4096
#define CCH   128
#define DI    256
#define NDIR  3
#define LT    (NDIR*L)
#define DS    16
#define NCHUNK 64
#define CHLEN  64
#define CTL   32

// ---------------- scratch ----------------
__device__ float g_xT[L*CCH];
__device__ float g_tok[L*CCH];
__device__ float g_xz[L*2*DI];
__device__ float g_xc[LT*DI];
__device__ float g_dbl[LT*40];
__device__ float g_delta[LT*DI];
__device__ float g_y[LT*DI];
__device__ float g_mo[LT*CCH];
__device__ float g_resT[L*CCH];
__device__ float g_hid[L*512];

typedef unsigned long long u64;

__device__ __forceinline__ void ffma2(u64 &d, u64 a, u64 b){
    asm("fma.rn.f32x2 %0, %1, %2, %0;" : "+l"(d) : "l"(a), "l"(b));
}
__device__ __forceinline__ u64 packdup(float v){
    u64 r; asm("mov.b64 %0, {%1, %1};" : "=l"(r) : "f"(v)); return r;
}
__device__ __forceinline__ void unpack2(u64 v, float &lo, float &hi){
    asm("mov.b64 {%0, %1}, %2;" : "=f"(lo), "=f"(hi) : "l"(v));
}

__device__ __forceinline__ int ptok(int dir, int l){
    int a = l >> 8, b = (l >> 4) & 15, c = l & 15;
    if (dir == 0) return l;
    if (dir == 1) return c*256 + a*16 + b;
    return b*256 + c*16 + a;
}
__device__ __forceinline__ int stol(int dir, int s){
    int a = s >> 8, b = (s >> 4) & 15, cc = s & 15;
    if (dir == 0) return s;
    if (dir == 1) return b*256 + cc*16 + a;
    return cc*256 + a*16 + b;
}

// ---------------- K1: fused transpose + double LayerNorm ----------------
__global__ void k_lnx(const float* __restrict__ x,
                      const float* __restrict__ lnw, const float* __restrict__ lnb,
                      const float* __restrict__ mw,  const float* __restrict__ mb){
    __shared__ float t[128][33];
    int s0 = blockIdx.x*32;
    int lane = threadIdx.x & 31, w = threadIdx.x >> 5;
    for (int r = w; r < 128; r += 8)
        t[r][lane] = x[(size_t)r*L + s0 + lane];
    __syncthreads();
    for (int round = 0; round < 4; round++){
        int tloc = round*8 + w;
        int s = s0 + tloc;
        float v[4];
        #pragma unroll
        for (int i = 0; i < 4; i++) v[i] = t[lane + 32*i][tloc];
        #pragma unroll
        for (int i = 0; i < 4; i++) g_xT[(size_t)s*CCH + lane + 32*i] = v[i];
        float sum = v[0]+v[1]+v[2]+v[3];
        #pragma unroll
        for (int o = 16; o; o >>= 1) sum += __shfl_xor_sync(0xffffffffu, sum, o);
        float mean = sum * (1.f/128.f);
        float d[4], var = 0.f;
        #pragma unroll
        for (int i = 0; i < 4; i++){ d[i] = v[i]-mean; var += d[i]*d[i]; }
        #pragma unroll
        for (int o = 16; o; o >>= 1) var += __shfl_xor_sync(0xffffffffu, var, o);
        float rs = rsqrtf(var*(1.f/128.f) + 1e-6f);
        float v1[4];
        #pragma unroll
        for (int i = 0; i < 4; i++){
            int c = lane + 32*i;
            v1[i] = d[i]*rs*lnw[c] + lnb[c];
        }
        float sum2 = v1[0]+v1[1]+v1[2]+v1[3];
        #pragma unroll
        for (int o = 16; o; o >>= 1) sum2 += __shfl_xor_sync(0xffffffffu, sum2, o);
        float mean2 = sum2 * (1.f/128.f);
        float d2[4], var2 = 0.f;
        #pragma unroll
        for (int i = 0; i < 4; i++){ d2[i] = v1[i]-mean2; var2 += d2[i]*d2[i]; }
        #pragma unroll
        for (int o = 16; o; o >>= 1) var2 += __shfl_xor_sync(0xffffffffu, var2, o);
        float rs2 = rsqrtf(var2*(1.f/128.f) + 1e-5f);
        #pragma unroll
        for (int i = 0; i < 4; i++){
            int c = lane + 32*i;
            g_tok[(size_t)s*CCH + c] = d2[i]*rs2*mw[c] + mb[c];
        }
    }
}

// ---------------- f32x2 tiled SGEMM (R3-proven) ----------------
// ACT: 0 none, 1 silu, 2 gelu(exact). PERM: A gathered from g_mo (3-dir). DELTA: fused delta epilogue.
template<int TM, int ACT, bool BIAS, bool RES, bool TSTORE, bool PERM, bool DELTA>
__global__ void k_tgemm(const float* __restrict__ A,
                        const float* __restrict__ W,
                        const float* __restrict__ bias,
                        const float* __restrict__ res,
                        float* __restrict__ out,
                        int N, int K,
                        const float* __restrict__ dtw,
                        const float* __restrict__ dtb){
    constexpr int TN = 64, KS = 16;
    constexpr int NP = TM/32;              // f32x2 row-pairs per thread
    constexpr int AL = (TM + 63)/64;       // A loads per thread
    __shared__ float As[KS][TM+4];
    __shared__ float Bs[KS][TN+4];
    __shared__ float sdt[DELTA ? 32 : 1][8];
    int tid = threadIdx.x;
    int tx = tid & 15, ty = tid >> 4;
    int lkq = tid & 3, lm = tid >> 2;
    int m0 = blockIdx.x * TM, n0 = blockIdx.y * TN;

    u64 acc[NP][4];
    #pragma unroll
    for (int p = 0; p < NP; p++)
        #pragma unroll
        for (int j = 0; j < 4; j++) acc[p][j] = 0ull;

    float4 ra[AL]; float4 rb;
    auto loadA = [&](int m, int k)->float4{
        if (!PERM) return *(const float4*)(A + (size_t)m*K + k);
        int dir = k >> 7, c = k & 127;
        int l = stol(dir, m);
        return *(const float4*)(A + ((size_t)(dir*L + l)*CCH + c));
    };
    auto loadTile = [&](int k0){
        #pragma unroll
        for (int i = 0; i < AL; i++){
            int m = lm + i*64;
            if (m < TM) ra[i] = loadA(m0 + m, k0 + lkq*4);
        }
        int n = n0 + lm;
        rb = make_float4(0.f,0.f,0.f,0.f);
        if (n < N) rb = *(const float4*)(W + (size_t)n*K + k0 + lkq*4);
    };
    auto storeTile = [&](){
        #pragma unroll
        for (int i = 0; i < AL; i++){
            int m = lm + i*64;
            if (m < TM){
                As[lkq*4+0][m] = ra[i].x; As[lkq*4+1][m] = ra[i].y;
                As[lkq*4+2][m] = ra[i].z; As[lkq*4+3][m] = ra[i].w;
            }
        }
        Bs[lkq*4+0][lm] = rb.x; Bs[lkq*4+1][lm] = rb.y;
        Bs[lkq*4+2][lm] = rb.z; Bs[lkq*4+3][lm] = rb.w;
    };

    int NT = K / KS;
    loadTile(0);
    for (int t = 0; t < NT; t++){
        storeTile();
        __syncthreads();
        if (t + 1 < NT) loadTile((t+1)*KS);
        #pragma unroll
        for (int kk = 0; kk < KS; kk++){
            float4 bv = *(const float4*)&Bs[kk][tx*4];
            u64 bd[4];
            bd[0] = packdup(bv.x); bd[1] = packdup(bv.y);
            bd[2] = packdup(bv.z); bd[3] = packdup(bv.w);
            u64 ap[NP];
            if (TM == 32){
                ap[0] = *(const u64*)&As[kk][ty*2];
            } else if (TM == 64){
                const u64* p = (const u64*)&As[kk][ty*4];
                ap[0] = p[0]; ap[1] = p[1];
            } else {
                const u64* p0 = (const u64*)&As[kk][ty*4];
                const u64* p1 = (const u64*)&As[kk][64 + ty*4];
                ap[0] = p0[0]; ap[1] = p0[1]; ap[2] = p1[0]; ap[3] = p1[1];
            }
            #pragma unroll
            for (int p = 0; p < NP; p++)
                #pragma unroll
                for (int j = 0; j < 4; j++)
                    ffma2(acc[p][j], ap[p], bd[j]);
        }
        __syncthreads();
    }

    #pragma unroll
    for (int p = 0; p < NP; p++){
        int rbase = (TM == 32) ? ty*2
                  : (TM == 64) ? ty*4 + (p & 1)*2
                  : (p >> 1)*64 + ty*4 + (p & 1)*2;
        #pragma unroll
        for (int j = 0; j < 4; j++){
            int n = n0 + tx*4 + j;
            if (n >= N) continue;
            float lo, hi;
            unpack2(acc[p][j], lo, hi);
            #pragma unroll
            for (int half = 0; half < 2; half++){
                int mr = rbase + half;
                int m = m0 + mr;
                float v = half ? hi : lo;
                if (BIAS) v += bias[n];
                if (ACT == 1)      v = v / (1.f + __expf(-v));
                else if (ACT == 2) v = 0.5f * v * (1.f + erff(v * 0.70710678118654752f));
                if (RES) v += res[(size_t)m*N + n];
                if (TSTORE) out[(size_t)n*L + m] = v;
                else        out[(size_t)m*N + n] = v;
                if (DELTA && n < 8) sdt[mr][n] = v;
            }
        }
    }

    if (DELTA){
        __syncthreads();
        int d = tid;
        float wr[8];
        #pragma unroll
        for (int r = 0; r < 8; r++) wr[r] = dtw[d*8 + r];
        float b = dtb[d];
        for (int tt = 0; tt < 32; tt++){
            float a = b;
            #pragma unroll
            for (int r = 0; r < 8; r++) a = fmaf(wr[r], sdt[tt][r], a);
            a = (a > 20.f) ? a : log1pf(__expf(a));
            g_delta[(size_t)(m0 + tt)*DI + d] = a;
        }
    }
}

// ---------------- K3: tiled causal depthwise conv + silu ----------------
__global__ void k_conv(const float* __restrict__ cw, const float* __restrict__ cb){
    __shared__ float sx[CTL+3][DI];
    int dir = blockIdx.y, l0 = blockIdx.x*CTL, ch = threadIdx.x;
    for (int r = 0; r < CTL+3; r++){
        int row = l0 - 3 + r;
        sx[r][ch] = (row >= 0) ? g_xz[(size_t)ptok(dir, row)*(2*DI) + ch] : 0.f;
    }
    __syncthreads();
    float w0 = cw[ch*4+0], w1 = cw[ch*4+1], w2 = cw[ch*4+2], w3 = cw[ch*4+3];
    float b = cb[ch];
    for (int i = 0; i < CTL; i++){
        float acc = b + w0*sx[i][ch] + w1*sx[i+1][ch] + w2*sx[i+2][ch] + w3*sx[i+3][ch];
        acc = acc / (1.f + __expf(-acc));
        g_xc[(size_t)(dir*L + l0 + i)*DI + ch] = acc;
    }
}

// ---------------- fused selective scan: block per (dir, d) ----------------
__global__ void __launch_bounds__(1024) k_scan(const float* __restrict__ Alog,
                                               const float* __restrict__ Dp){
    __shared__ float sP[NCHUNK][DS];
    __shared__ float sS[NCHUNK][DS];
    int bx = blockIdx.x;
    int dir = bx >> 8, d = bx & 255;
    int tid = threadIdx.x;
    int chunk = tid >> 4, n = tid & 15;
    float Av = -__expf(Alog[d*DS + n]);
    int base = dir*L + chunk*CHLEN;

    // pass A: chunk summaries
    float P = 1.f, S = 0.f;
    for (int st = 0; st < CHLEN; st++){
        int lg = base + st;
        float dl = g_delta[(size_t)lg*DI + d];
        float u  = g_xc  [(size_t)lg*DI + d];
        float Bv = g_dbl [(size_t)lg*40 + 8 + n];
        float a  = __expf(dl * Av);
        P *= a;
        S = a*S + dl*Bv*u;
    }
    sP[chunk][n] = P; sS[chunk][n] = S;
    __syncthreads();

    // Kogge-Stone inclusive scan over chunks
    #pragma unroll
    for (int off = 1; off < NCHUNK; off <<= 1){
        float pP = 1.f, pS = 0.f;
        if (chunk >= off){ pP = sP[chunk-off][n]; pS = sS[chunk-off][n]; }
        __syncthreads();
        S = fmaf(P, pS, S);
        P *= pP;
        sP[chunk][n] = P; sS[chunk][n] = S;
        __syncthreads();
    }
    float h = (chunk > 0) ? sS[chunk-1][n] : 0.f;

    // pass C: recompute with correct h0 + C-dot + D skip + silu(z) gate
    float Dv = Dp[d];
    for (int st = 0; st < CHLEN; st++){
        int lg = base + st;
        float dl = g_delta[(size_t)lg*DI + d];
        float u  = g_xc  [(size_t)lg*DI + d];
        float Bv = g_dbl [(size_t)lg*40 + 8 + n];
        float Cv = g_dbl [(size_t)lg*40 + 24 + n];
        float a  = __expf(dl * Av);
        h = a*h + dl*Bv*u;
        float p = h * Cv;
        p += __shfl_xor_sync(0xffffffffu, p, 8);
        p += __shfl_xor_sync(0xffffffffu, p, 4);
        p += __shfl_xor_sync(0xffffffffu, p, 2);
        p += __shfl_xor_sync(0xffffffffu, p, 1);
        if (n == 0){
            int l = chunk*CHLEN + st;
            float z = g_xz[(size_t)ptok(dir, l)*(2*DI) + DI + d];
            float yy = (p + u*Dv) * (z / (1.f + __expf(-z)));
            g_y[(size_t)lg*DI + d] = yy;
        }
    }
}

// ---------------- LN over channels of out_res ----------------
__device__ __forceinline__ float bsum128(float v, float* sh){
    #pragma unroll
    for (int o = 16; o; o >>= 1) v += __shfl_xor_sync(0xffffffffu, v, o);
    __syncthreads();
    if ((threadIdx.x & 31) == 0) sh[threadIdx.x >> 5] = v;
    __syncthreads();
    return sh[0] + sh[1] + sh[2] + sh[3];
}
__global__ void k_ln_res(const float* __restrict__ lnw, const float* __restrict__ lnb){
    __shared__ float sh[4];
    int s = blockIdx.x, c = threadIdx.x;
    float v   = g_resT[(size_t)s*CCH + c];
    float m   = bsum128(v, sh) * (1.f/128.f);
    float d   = v - m;
    float var = bsum128(d*d, sh) * (1.f/128.f);
    g_tok[(size_t)s*CCH + c] = d * rsqrtf(var + 1e-6f) * lnw[c] + lnb[c];
}

// ---------------- launch ----------------
extern "C" void kernel_launch(void* const* d_in, const int* in_sizes, int n_in,
                              void* d_out, int out_size){
    const float* x        = (const float*)d_in[0];
    const float* ln_w     = (const float*)d_in[1];
    const float* ln_b     = (const float*)d_in[2];
    const float* mnorm_w  = (const float*)d_in[3];
    const float* mnorm_b  = (const float*)d_in[4];
    const float* in_proj  = (const float*)d_in[5];
    const float* conv_w   = (const float*)d_in[6];
    const float* conv_b   = (const float*)d_in[7];
    const float* x_proj   = (const float*)d_in[8];
    const float* dt_proj  = (const float*)d_in[9];
    const float* dt_bias  = (const float*)d_in[10];
    const float* A_log    = (const float*)d_in[11];
    const float* D_param  = (const float*)d_in[12];
    const float* out_proj = (const float*)d_in[13];
    const float* proj_w   = (const float*)d_in[14];
    const float* proj_b   = (const float*)d_in[15];
    const float* fc1_w    = (const float*)d_in[16];
    const float* fc1_b    = (const float*)d_in[17];
    const float* fc2_w    = (const float*)d_in[18];
    const float* fc2_b    = (const float*)d_in[19];
    float* out = (float*)d_out;

    void *p_tok, *p_xz, *p_xc, *p_dbl, *p_y, *p_mo, *p_resT, *p_hid, *p_xT;
    cudaGetSymbolAddress(&p_tok,  g_tok);
    cudaGetSymbolAddress(&p_xz,   g_xz);
    cudaGetSymbolAddress(&p_xc,   g_xc);
    cudaGetSymbolAddress(&p_dbl,  g_dbl);
    cudaGetSymbolAddress(&p_y,    g_y);
    cudaGetSymbolAddress(&p_mo,   g_mo);
    cudaGetSymbolAddress(&p_resT, g_resT);
    cudaGetSymbolAddress(&p_hid,  g_hid);
    cudaGetSymbolAddress(&p_xT,   g_xT);

    // 1. fused transpose + double token LN
    k_lnx<<<L/32, 256>>>(x, ln_w, ln_b, mnorm_w, mnorm_b);
    // 2. in_proj: [4096,128]@[512,128]^T  (TM=64 -> 512 blocks, was 256)
    k_tgemm<64,0,false,false,false,false,false><<<dim3(L/64, 8), 256>>>(
        (const float*)p_tok, in_proj, nullptr, nullptr, (float*)p_xz, 512, 128, nullptr, nullptr);
    // 3. tiled causal conv + silu
    k_conv<<<dim3(L/CTL, NDIR), DI>>>(conv_w, conv_b);
    // 4. x_dbl GEMM + fused delta epilogue
    k_tgemm<32,0,false,false,false,false,true><<<dim3(LT/32, 1), 256>>>(
        (const float*)p_xc, x_proj, nullptr, nullptr, (float*)p_dbl, 40, 256, dt_proj, dt_bias);
    // 5. fused selective scan (A + combine + C)
    k_scan<<<NDIR*DI, 1024>>>(A_log, D_param);
    // 6. out_proj: [12288,256]@[128,256]^T  (TM=32 -> 768 blocks, was 384)
    k_tgemm<32,0,false,false,false,false,false><<<dim3(LT/32, 2), 256>>>(
        (const float*)p_y, out_proj, nullptr, nullptr, (float*)p_mo, 128, 256, nullptr, nullptr);
    // 7. proj(384->128) with fused 3-dir gather in A-load + bias + x residual
    k_tgemm<32,0,true,true,false,true,false><<<dim3(L/32, 2), 256>>>(
        (const float*)p_mo, proj_w, proj_b, (const float*)p_xT, (float*)p_resT, 128, 384, nullptr, nullptr);
    // 8. LN(out_res)
    k_ln_res<<<L, 128>>>(ln_w, ln_b);
    // 9. fc1 + exact GELU  (TM=64 -> 512 blocks, was 256)
    k_tgemm<64,2,true,false,false,false,false><<<dim3(L/64, 8), 256>>>(
        (const float*)p_tok, fc1_w, fc1_b, nullptr, (float*)p_hid, 512, 128, nullptr, nullptr);
    // 10. fc2 + bias + residual + transposed store to (C,D,H,W)
    k_tgemm<32,0,true,true,true,false,false><<<dim3(L/32, 2), 256>>>(
        (const float*)p_hid, fc2_w, fc2_b, (const float*)p_resT, out, 128, 512, nullptr, nullptr);
}

// round 8
// speedup vs baseline: 1.3314x; 1.0853x over previous
#include <cuda_runtime.h>
#include <math.h>

#define L     4096
#define CCH   128
#define DI    256
#define NDIR  3
#define LT    (NDIR*L)
#define DS    16
#define NCHUNK 64
#define CHLEN  64
#define CTL   32

// ---------------- scratch ----------------
__device__ float g_xT[L*CCH];
__device__ float g_tok[L*CCH];
__device__ float g_xz[L*2*DI];
__device__ float g_xc[LT*DI];
__device__ float g_dbl[LT*40];
__device__ float g_delta[LT*DI];
__device__ float g_y[LT*DI];
__device__ float g_pp[NDIR*L*CCH];    // dir-split partials of out1
__device__ float g_wf[CCH*NDIR*DI];   // fused weights: wf[o][dir*256+k]
__device__ float g_resT[L*CCH];
__device__ float g_hid[L*512];

typedef unsigned long long u64;

__device__ __forceinline__ void ffma2(u64 &d, u64 a, u64 b){
    asm("fma.rn.f32x2 %0, %1, %2, %0;" : "+l"(d) : "l"(a), "l"(b));
}
__device__ __forceinline__ u64 packdup(float v){
    u64 r; asm("mov.b64 %0, {%1, %1};" : "=l"(r) : "f"(v)); return r;
}
__device__ __forceinline__ void unpack2(u64 v, float &lo, float &hi){
    asm("mov.b64 {%0, %1}, %2;" : "=f"(lo), "=f"(hi) : "l"(v));
}

__device__ __forceinline__ int ptok(int dir, int l){
    int a = l >> 8, b = (l >> 4) & 15, c = l & 15;
    if (dir == 0) return l;
    if (dir == 1) return c*256 + a*16 + b;
    return b*256 + c*16 + a;
}
__device__ __forceinline__ int stol(int dir, int s){
    int a = s >> 8, b = (s >> 4) & 15, cc = s & 15;
    if (dir == 0) return s;
    if (dir == 1) return b*256 + cc*16 + a;
    return cc*256 + a*16 + b;
}

// ---------------- K1: fused transpose + double LayerNorm ----------------
__global__ void k_lnx(const float* __restrict__ x,
                      const float* __restrict__ lnw, const float* __restrict__ lnb,
                      const float* __restrict__ mw,  const float* __restrict__ mb){
    __shared__ float t[128][33];
    int s0 = blockIdx.x*32;
    int lane = threadIdx.x & 31, w = threadIdx.x >> 5;
    for (int r = w; r < 128; r += 8)
        t[r][lane] = x[(size_t)r*L + s0 + lane];
    __syncthreads();
    for (int round = 0; round < 4; round++){
        int tloc = round*8 + w;
        int s = s0 + tloc;
        float v[4];
        #pragma unroll
        for (int i = 0; i < 4; i++) v[i] = t[lane + 32*i][tloc];
        #pragma unroll
        for (int i = 0; i < 4; i++) g_xT[(size_t)s*CCH + lane + 32*i] = v[i];
        float sum = v[0]+v[1]+v[2]+v[3];
        #pragma unroll
        for (int o = 16; o; o >>= 1) sum += __shfl_xor_sync(0xffffffffu, sum, o);
        float mean = sum * (1.f/128.f);
        float d[4], var = 0.f;
        #pragma unroll
        for (int i = 0; i < 4; i++){ d[i] = v[i]-mean; var += d[i]*d[i]; }
        #pragma unroll
        for (int o = 16; o; o >>= 1) var += __shfl_xor_sync(0xffffffffu, var, o);
        float rs = rsqrtf(var*(1.f/128.f) + 1e-6f);
        float v1[4];
        #pragma unroll
        for (int i = 0; i < 4; i++){
            int c = lane + 32*i;
            v1[i] = d[i]*rs*lnw[c] + lnb[c];
        }
        float sum2 = v1[0]+v1[1]+v1[2]+v1[3];
        #pragma unroll
        for (int o = 16; o; o >>= 1) sum2 += __shfl_xor_sync(0xffffffffu, sum2, o);
        float mean2 = sum2 * (1.f/128.f);
        float d2[4], var2 = 0.f;
        #pragma unroll
        for (int i = 0; i < 4; i++){ d2[i] = v1[i]-mean2; var2 += d2[i]*d2[i]; }
        #pragma unroll
        for (int o = 16; o; o >>= 1) var2 += __shfl_xor_sync(0xffffffffu, var2, o);
        float rs2 = rsqrtf(var2*(1.f/128.f) + 1e-5f);
        #pragma unroll
        for (int i = 0; i < 4; i++){
            int c = lane + 32*i;
            g_tok[(size_t)s*CCH + c] = d2[i]*rs2*mw[c] + mb[c];
        }
    }
}

// ---------------- f32x2 tiled SGEMM (R3-proven inner loop) ----------------
// ACT: 0 none, 2 gelu(exact). AMODE: 0 plain A[m][k]; 2 dir-gathered from g_y (dir=blockIdx.z).
// DELTA: fused delta epilogue. SPLITD: z-indexed W offset + partial output.
template<int TM, int ACT, bool BIAS, bool RES, bool TSTORE, int AMODE, bool DELTA, bool SPLITD>
__global__ void k_tgemm(const float* __restrict__ A,
                        const float* __restrict__ W,
                        const float* __restrict__ bias,
                        const float* __restrict__ res,
                        float* __restrict__ out,
                        int N, int K, int wstride,
                        const float* __restrict__ dtw,
                        const float* __restrict__ dtb){
    constexpr int TN = 64, KS = 16;
    constexpr int NP = TM/32;              // f32x2 row-pairs per thread
    constexpr int AL = (TM + 63)/64;       // A loads per thread
    __shared__ float As[KS][TM+4];
    __shared__ float Bs[KS][TN+4];
    __shared__ float sdt[DELTA ? 32 : 1][8];
    int tid = threadIdx.x;
    int tx = tid & 15, ty = tid >> 4;
    int lkq = tid & 3, lm = tid >> 2;
    int m0 = blockIdx.x * TM, n0 = blockIdx.y * TN;
    int dir = SPLITD ? blockIdx.z : 0;
    int woff = SPLITD ? dir*K : 0;

    u64 acc[NP][4];
    #pragma unroll
    for (int p = 0; p < NP; p++)
        #pragma unroll
        for (int j = 0; j < 4; j++) acc[p][j] = 0ull;

    float4 ra[AL]; float4 rb;
    auto loadA = [&](int m, int k)->float4{
        if (AMODE == 2){
            int l = stol(dir, m);
            return *(const float4*)(A + ((size_t)(dir*L + l)*DI + k));
        }
        return *(const float4*)(A + (size_t)m*K + k);
    };
    auto loadTile = [&](int k0){
        #pragma unroll
        for (int i = 0; i < AL; i++){
            int m = lm + i*64;
            if (m < TM) ra[i] = loadA(m0 + m, k0 + lkq*4);
        }
        int n = n0 + lm;
        rb = make_float4(0.f,0.f,0.f,0.f);
        if (n < N) rb = *(const float4*)(W + (size_t)n*wstride + woff + k0 + lkq*4);
    };
    auto storeTile = [&](){
        #pragma unroll
        for (int i = 0; i < AL; i++){
            int m = lm + i*64;
            if (m < TM){
                As[lkq*4+0][m] = ra[i].x; As[lkq*4+1][m] = ra[i].y;
                As[lkq*4+2][m] = ra[i].z; As[lkq*4+3][m] = ra[i].w;
            }
        }
        Bs[lkq*4+0][lm] = rb.x; Bs[lkq*4+1][lm] = rb.y;
        Bs[lkq*4+2][lm] = rb.z; Bs[lkq*4+3][lm] = rb.w;
    };

    int NT = K / KS;
    loadTile(0);
    for (int t = 0; t < NT; t++){
        storeTile();
        __syncthreads();
        if (t + 1 < NT) loadTile((t+1)*KS);
        #pragma unroll
        for (int kk = 0; kk < KS; kk++){
            float4 bv = *(const float4*)&Bs[kk][tx*4];
            u64 bd[4];
            bd[0] = packdup(bv.x); bd[1] = packdup(bv.y);
            bd[2] = packdup(bv.z); bd[3] = packdup(bv.w);
            u64 ap[NP];
            if (TM == 32){
                ap[0] = *(const u64*)&As[kk][ty*2];
            } else if (TM == 64){
                const u64* p = (const u64*)&As[kk][ty*4];
                ap[0] = p[0]; ap[1] = p[1];
            } else {
                const u64* p0 = (const u64*)&As[kk][ty*4];
                const u64* p1 = (const u64*)&As[kk][64 + ty*4];
                ap[0] = p0[0]; ap[1] = p0[1]; ap[2] = p1[0]; ap[3] = p1[1];
            }
            #pragma unroll
            for (int p = 0; p < NP; p++)
                #pragma unroll
                for (int j = 0; j < 4; j++)
                    ffma2(acc[p][j], ap[p], bd[j]);
        }
        __syncthreads();
    }

    #pragma unroll
    for (int p = 0; p < NP; p++){
        int rbase = (TM == 32) ? ty*2
                  : (TM == 64) ? ty*4 + (p & 1)*2
                  : (p >> 1)*64 + ty*4 + (p & 1)*2;
        #pragma unroll
        for (int j = 0; j < 4; j++){
            int n = n0 + tx*4 + j;
            if (n >= N) continue;
            float lo, hi;
            unpack2(acc[p][j], lo, hi);
            #pragma unroll
            for (int half = 0; half < 2; half++){
                int mr = rbase + half;
                int m = m0 + mr;
                float v = half ? hi : lo;
                if (BIAS) v += bias[n];
                if (ACT == 2) v = 0.5f * v * (1.f + erff(v * 0.70710678118654752f));
                if (RES) v += res[(size_t)m*N + n];
                if (SPLITD)      out[(size_t)dir*L*CCH + (size_t)m*N + n] = v;
                else if (TSTORE) out[(size_t)n*L + m] = v;
                else             out[(size_t)m*N + n] = v;
                if (DELTA && n < 8) sdt[mr][n] = v;
            }
        }
    }

    if (DELTA){
        __syncthreads();
        int d = tid;
        float wr[8];
        #pragma unroll
        for (int r = 0; r < 8; r++) wr[r] = dtw[d*8 + r];
        float b = dtb[d];
        for (int tt = 0; tt < 32; tt++){
            float a = b;
            #pragma unroll
            for (int r = 0; r < 8; r++) a = fmaf(wr[r], sdt[tt][r], a);
            a = (a > 20.f) ? a : log1pf(__expf(a));
            g_delta[(size_t)(m0 + tt)*DI + d] = a;
        }
    }
}

// ---------------- Wf = proj_w[:, dir block] @ out_proj ----------------
__global__ void k_wfuse(const float* __restrict__ pw, const float* __restrict__ op){
    __shared__ float spw[3*CCH];
    int o = blockIdx.x, k = threadIdx.x;      // 128 blocks, 256 threads
    for (int i = k; i < 3*CCH; i += 256) spw[i] = pw[o*3*CCH + i];
    __syncthreads();
    float a0 = 0.f, a1 = 0.f, a2 = 0.f;
    for (int c = 0; c < CCH; c++){
        float v = op[(size_t)c*DI + k];
        a0 = fmaf(spw[c],       v, a0);
        a1 = fmaf(spw[CCH+c],   v, a1);
        a2 = fmaf(spw[2*CCH+c], v, a2);
    }
    g_wf[(size_t)o*(NDIR*DI) + k]        = a0;
    g_wf[(size_t)o*(NDIR*DI) + DI + k]   = a1;
    g_wf[(size_t)o*(NDIR*DI) + 2*DI + k] = a2;
}

// ---------------- K3: tiled causal depthwise conv + silu ----------------
__global__ void k_conv(const float* __restrict__ cw, const float* __restrict__ cb){
    __shared__ float sx[CTL+3][DI];
    int dir = blockIdx.y, l0 = blockIdx.x*CTL, ch = threadIdx.x;
    for (int r = 0; r < CTL+3; r++){
        int row = l0 - 3 + r;
        sx[r][ch] = (row >= 0) ? g_xz[(size_t)ptok(dir, row)*(2*DI) + ch] : 0.f;
    }
    __syncthreads();
    float w0 = cw[ch*4+0], w1 = cw[ch*4+1], w2 = cw[ch*4+2], w3 = cw[ch*4+3];
    float b = cb[ch];
    for (int i = 0; i < CTL; i++){
        float acc = b + w0*sx[i][ch] + w1*sx[i+1][ch] + w2*sx[i+2][ch] + w3*sx[i+3][ch];
        acc = acc / (1.f + __expf(-acc));
        g_xc[(size_t)(dir*L + l0 + i)*DI + ch] = acc;
    }
}

// ---------------- fused selective scan: block per (dir, d) ----------------
__global__ void __launch_bounds__(1024) k_scan(const float* __restrict__ Alog,
                                               const float* __restrict__ Dp){
    __shared__ float sP[NCHUNK][DS];
    __shared__ float sS[NCHUNK][DS];
    int bx = blockIdx.x;
    int dir = bx >> 8, d = bx & 255;
    int tid = threadIdx.x;
    int chunk = tid >> 4, n = tid & 15;
    float Av = -__expf(Alog[d*DS + n]);
    int base = dir*L + chunk*CHLEN;

    float P = 1.f, S = 0.f;
    for (int st = 0; st < CHLEN; st++){
        int lg = base + st;
        float dl = g_delta[(size_t)lg*DI + d];
        float u  = g_xc  [(size_t)lg*DI + d];
        float Bv = g_dbl [(size_t)lg*40 + 8 + n];
        float a  = __expf(dl * Av);
        P *= a;
        S = a*S + dl*Bv*u;
    }
    sP[chunk][n] = P; sS[chunk][n] = S;
    __syncthreads();

    #pragma unroll
    for (int off = 1; off < NCHUNK; off <<= 1){
        float pP = 1.f, pS = 0.f;
        if (chunk >= off){ pP = sP[chunk-off][n]; pS = sS[chunk-off][n]; }
        __syncthreads();
        S = fmaf(P, pS, S);
        P *= pP;
        sP[chunk][n] = P; sS[chunk][n] = S;
        __syncthreads();
    }
    float h = (chunk > 0) ? sS[chunk-1][n] : 0.f;

    float Dv = Dp[d];
    for (int st = 0; st < CHLEN; st++){
        int lg = base + st;
        float dl = g_delta[(size_t)lg*DI + d];
        float u  = g_xc  [(size_t)lg*DI + d];
        float Bv = g_dbl [(size_t)lg*40 + 8 + n];
        float Cv = g_dbl [(size_t)lg*40 + 24 + n];
        float a  = __expf(dl * Av);
        h = a*h + dl*Bv*u;
        float p = h * Cv;
        p += __shfl_xor_sync(0xffffffffu, p, 8);
        p += __shfl_xor_sync(0xffffffffu, p, 4);
        p += __shfl_xor_sync(0xffffffffu, p, 2);
        p += __shfl_xor_sync(0xffffffffu, p, 1);
        if (n == 0){
            int l = chunk*CHLEN + st;
            float z = g_xz[(size_t)ptok(dir, l)*(2*DI) + DI + d];
            float yy = (p + u*Dv) * (z / (1.f + __expf(-z)));
            g_y[(size_t)lg*DI + d] = yy;
        }
    }
}

// ---------------- fused: sum 3 dir-partials + bias + x residual -> resT; then LN -> tok ----------------
__device__ __forceinline__ float bsum128(float v, float* sh){
    #pragma unroll
    for (int o = 16; o; o >>= 1) v += __shfl_xor_sync(0xffffffffu, v, o);
    __syncthreads();
    if ((threadIdx.x & 31) == 0) sh[threadIdx.x >> 5] = v;
    __syncthreads();
    return sh[0] + sh[1] + sh[2] + sh[3];
}
__global__ void k_ln_res(const float* __restrict__ pb,
                         const float* __restrict__ lnw, const float* __restrict__ lnb){
    __shared__ float sh[4];
    int s = blockIdx.x, c = threadIdx.x;
    float v = g_pp[(size_t)s*CCH + c]
            + g_pp[(size_t)(L + s)*CCH + c]
            + g_pp[(size_t)(2*L + s)*CCH + c]
            + pb[c] + g_xT[(size_t)s*CCH + c];
    g_resT[(size_t)s*CCH + c] = v;
    float m   = bsum128(v, sh) * (1.f/128.f);
    float d   = v - m;
    float var = bsum128(d*d, sh) * (1.f/128.f);
    g_tok[(size_t)s*CCH + c] = d * rsqrtf(var + 1e-6f) * lnw[c] + lnb[c];
}

// ---------------- launch ----------------
extern "C" void kernel_launch(void* const* d_in, const int* in_sizes, int n_in,
                              void* d_out, int out_size){
    const float* x        = (const float*)d_in[0];
    const float* ln_w     = (const float*)d_in[1];
    const float* ln_b     = (const float*)d_in[2];
    const float* mnorm_w  = (const float*)d_in[3];
    const float* mnorm_b  = (const float*)d_in[4];
    const float* in_proj  = (const float*)d_in[5];
    const float* conv_w   = (const float*)d_in[6];
    const float* conv_b   = (const float*)d_in[7];
    const float* x_proj   = (const float*)d_in[8];
    const float* dt_proj  = (const float*)d_in[9];
    const float* dt_bias  = (const float*)d_in[10];
    const float* A_log    = (const float*)d_in[11];
    const float* D_param  = (const float*)d_in[12];
    const float* out_proj = (const float*)d_in[13];
    const float* proj_w   = (const float*)d_in[14];
    const float* proj_b   = (const float*)d_in[15];
    const float* fc1_w    = (const float*)d_in[16];
    const float* fc1_b    = (const float*)d_in[17];
    const float* fc2_w    = (const float*)d_in[18];
    const float* fc2_b    = (const float*)d_in[19];
    float* out = (float*)d_out;

    void *p_tok, *p_xz, *p_xc, *p_dbl, *p_y, *p_pp, *p_wf, *p_resT, *p_hid;
    cudaGetSymbolAddress(&p_tok,  g_tok);
    cudaGetSymbolAddress(&p_xz,   g_xz);
    cudaGetSymbolAddress(&p_xc,   g_xc);
    cudaGetSymbolAddress(&p_dbl,  g_dbl);
    cudaGetSymbolAddress(&p_y,    g_y);
    cudaGetSymbolAddress(&p_pp,   g_pp);
    cudaGetSymbolAddress(&p_wf,   g_wf);
    cudaGetSymbolAddress(&p_resT, g_resT);
    cudaGetSymbolAddress(&p_hid,  g_hid);

    // 0. fused weights Wf = proj_w_dir @ out_proj (independent of activations)
    k_wfuse<<<CCH, 256>>>(proj_w, out_proj);
    // 1. fused transpose + double token LN
    k_lnx<<<L/32, 256>>>(x, ln_w, ln_b, mnorm_w, mnorm_b);
    // 2. in_proj: [4096,128]@[512,128]^T  (R3 config)
    k_tgemm<128,0,false,false,false,0,false,false><<<dim3(L/128, 8), 256>>>(
        (const float*)p_tok, in_proj, nullptr, nullptr, (float*)p_xz, 512, 128, 128, nullptr, nullptr);
    // 3. tiled causal conv + silu
    k_conv<<<dim3(L/CTL, NDIR), DI>>>(conv_w, conv_b);
    // 4. x_dbl GEMM + fused delta epilogue (R3 config)
    k_tgemm<32,0,false,false,false,0,true,false><<<dim3(LT/32, 1), 256>>>(
        (const float*)p_xc, x_proj, nullptr, nullptr, (float*)p_dbl, 40, 256, 256, dt_proj, dt_bias);
    // 5. fused selective scan
    k_scan<<<NDIR*DI, 1024>>>(A_log, D_param);
    // 6. dir-split fused (out_proj∘proj) GEMM: partials pp[dir][s][o]
    k_tgemm<128,0,false,false,false,2,false,true><<<dim3(L/128, 2, NDIR), 256>>>(
        (const float*)p_y, (const float*)p_wf, nullptr, nullptr, (float*)p_pp, 128, 256, NDIR*DI, nullptr, nullptr);
    // 7. sum partials + proj_b + x residual -> resT, then LN -> tok
    k_ln_res<<<L, 128>>>(proj_b, ln_w, ln_b);
    // 8. fc1 + exact GELU (R3 config)
    k_tgemm<128,2,true,false,false,0,false,false><<<dim3(L/128, 8), 256>>>(
        (const float*)p_tok, fc1_w, fc1_b, nullptr, (float*)p_hid, 512, 128, 128, nullptr, nullptr);
    // 9. fc2 + bias + residual + transposed store to (C,D,H,W) (R3 config)
    k_tgemm<32,0,true,true,true,0,false,false><<<dim3(L/32, 2), 256>>>(
        (const float*)p_hid, fc2_w, fc2_b, (const float*)p_resT, out, 128, 512, 512, nullptr, nullptr);
}

// round 9
// speedup vs baseline: 1.3477x; 1.0122x over previous
#include <cuda_runtime.h>
#include <math.h>

#define L     4096
#define CCH   128
#define DI    256
#define NDIR  3
#define LT    (NDIR*L)
#define DS    16
#define NCHUNK 64
#define CHLEN  64
#define CTL   32

// ---------------- scratch ----------------
__device__ float g_xT[L*CCH];
__device__ float g_tok[L*CCH];
__device__ float g_xz[L*2*DI];
__device__ float g_xc[LT*DI];
__device__ float g_dbl[LT*40];
__device__ float g_delta[LT*DI];
__device__ float g_y[LT*DI];
__device__ float g_pp[NDIR*L*CCH];    // dir-split partials of out1
__device__ float g_wf[CCH*NDIR*DI];   // fused weights: wf[o][dir*256+k]
__device__ float g_resT[L*CCH];
__device__ float g_hid[L*512];

typedef unsigned long long u64;

__device__ __forceinline__ void ffma2(u64 &d, u64 a, u64 b){
    asm("fma.rn.f32x2 %0, %1, %2, %0;" : "+l"(d) : "l"(a), "l"(b));
}
__device__ __forceinline__ u64 packdup(float v){
    u64 r; asm("mov.b64 %0, {%1, %1};" : "=l"(r) : "f"(v)); return r;
}
__device__ __forceinline__ void unpack2(u64 v, float &lo, float &hi){
    asm("mov.b64 {%0, %1}, %2;" : "=f"(lo), "=f"(hi) : "l"(v));
}

__device__ __forceinline__ int ptok(int dir, int l){
    int a = l >> 8, b = (l >> 4) & 15, c = l & 15;
    if (dir == 0) return l;
    if (dir == 1) return c*256 + a*16 + b;
    return b*256 + c*16 + a;
}
__device__ __forceinline__ int stol(int dir, int s){
    int a = s >> 8, b = (s >> 4) & 15, cc = s & 15;
    if (dir == 0) return s;
    if (dir == 1) return b*256 + cc*16 + a;
    return cc*256 + a*16 + b;
}

// ---------------- K1: fused transpose + double LayerNorm ----------------
__global__ void k_lnx(const float* __restrict__ x,
                      const float* __restrict__ lnw, const float* __restrict__ lnb,
                      const float* __restrict__ mw,  const float* __restrict__ mb){
    __shared__ float t[128][33];
    int s0 = blockIdx.x*32;
    int lane = threadIdx.x & 31, w = threadIdx.x >> 5;
    for (int r = w; r < 128; r += 8)
        t[r][lane] = x[(size_t)r*L + s0 + lane];
    __syncthreads();
    for (int round = 0; round < 4; round++){
        int tloc = round*8 + w;
        int s = s0 + tloc;
        float v[4];
        #pragma unroll
        for (int i = 0; i < 4; i++) v[i] = t[lane + 32*i][tloc];
        #pragma unroll
        for (int i = 0; i < 4; i++) g_xT[(size_t)s*CCH + lane + 32*i] = v[i];
        float sum = v[0]+v[1]+v[2]+v[3];
        #pragma unroll
        for (int o = 16; o; o >>= 1) sum += __shfl_xor_sync(0xffffffffu, sum, o);
        float mean = sum * (1.f/128.f);
        float d[4], var = 0.f;
        #pragma unroll
        for (int i = 0; i < 4; i++){ d[i] = v[i]-mean; var += d[i]*d[i]; }
        #pragma unroll
        for (int o = 16; o; o >>= 1) var += __shfl_xor_sync(0xffffffffu, var, o);
        float rs = rsqrtf(var*(1.f/128.f) + 1e-6f);
        float v1[4];
        #pragma unroll
        for (int i = 0; i < 4; i++){
            int c = lane + 32*i;
            v1[i] = d[i]*rs*lnw[c] + lnb[c];
        }
        float sum2 = v1[0]+v1[1]+v1[2]+v1[3];
        #pragma unroll
        for (int o = 16; o; o >>= 1) sum2 += __shfl_xor_sync(0xffffffffu, sum2, o);
        float mean2 = sum2 * (1.f/128.f);
        float d2[4], var2 = 0.f;
        #pragma unroll
        for (int i = 0; i < 4; i++){ d2[i] = v1[i]-mean2; var2 += d2[i]*d2[i]; }
        #pragma unroll
        for (int o = 16; o; o >>= 1) var2 += __shfl_xor_sync(0xffffffffu, var2, o);
        float rs2 = rsqrtf(var2*(1.f/128.f) + 1e-5f);
        #pragma unroll
        for (int i = 0; i < 4; i++){
            int c = lane + 32*i;
            g_tok[(size_t)s*CCH + c] = d2[i]*rs2*mw[c] + mb[c];
        }
    }
}

// ---------------- f32x2 tiled SGEMM (R3-proven inner loop) ----------------
// ACT: 0 none, 2 gelu(exact). AMODE: 0 plain A[m][k]; 2 dir-gathered from g_y (dir=blockIdx.z).
// DELTA: fused delta epilogue. SPLITD: z-indexed W offset + partial output.
template<int TM, int ACT, bool BIAS, bool RES, bool TSTORE, int AMODE, bool DELTA, bool SPLITD>
__global__ void k_tgemm(const float* __restrict__ A,
                        const float* __restrict__ W,
                        const float* __restrict__ bias,
                        const float* __restrict__ res,
                        float* __restrict__ out,
                        int N, int K, int wstride,
                        const float* __restrict__ dtw,
                        const float* __restrict__ dtb){
    constexpr int TN = 64, KS = 16;
    constexpr int NP = TM/32;              // f32x2 row-pairs per thread
    constexpr int AL = (TM + 63)/64;       // A loads per thread
    __shared__ float As[KS][TM+4];
    __shared__ float Bs[KS][TN+4];
    __shared__ float sdt[DELTA ? TM : 1][8];
    int tid = threadIdx.x;
    int tx = tid & 15, ty = tid >> 4;
    int lkq = tid & 3, lm = tid >> 2;
    int m0 = blockIdx.x * TM, n0 = blockIdx.y * TN;
    int dir = SPLITD ? blockIdx.z : 0;
    int woff = SPLITD ? dir*K : 0;

    u64 acc[NP][4];
    #pragma unroll
    for (int p = 0; p < NP; p++)
        #pragma unroll
        for (int j = 0; j < 4; j++) acc[p][j] = 0ull;

    float4 ra[AL]; float4 rb;
    auto loadA = [&](int m, int k)->float4{
        if (AMODE == 2){
            int l = stol(dir, m);
            return *(const float4*)(A + ((size_t)(dir*L + l)*DI + k));
        }
        return *(const float4*)(A + (size_t)m*K + k);
    };
    auto loadTile = [&](int k0){
        #pragma unroll
        for (int i = 0; i < AL; i++){
            int m = lm + i*64;
            if (m < TM) ra[i] = loadA(m0 + m, k0 + lkq*4);
        }
        int n = n0 + lm;
        rb = make_float4(0.f,0.f,0.f,0.f);
        if (n < N) rb = *(const float4*)(W + (size_t)n*wstride + woff + k0 + lkq*4);
    };
    auto storeTile = [&](){
        #pragma unroll
        for (int i = 0; i < AL; i++){
            int m = lm + i*64;
            if (m < TM){
                As[lkq*4+0][m] = ra[i].x; As[lkq*4+1][m] = ra[i].y;
                As[lkq*4+2][m] = ra[i].z; As[lkq*4+3][m] = ra[i].w;
            }
        }
        Bs[lkq*4+0][lm] = rb.x; Bs[lkq*4+1][lm] = rb.y;
        Bs[lkq*4+2][lm] = rb.z; Bs[lkq*4+3][lm] = rb.w;
    };

    int NT = K / KS;
    loadTile(0);
    for (int t = 0; t < NT; t++){
        storeTile();
        __syncthreads();
        if (t + 1 < NT) loadTile((t+1)*KS);
        #pragma unroll
        for (int kk = 0; kk < KS; kk++){
            float4 bv = *(const float4*)&Bs[kk][tx*4];
            u64 bd[4];
            bd[0] = packdup(bv.x); bd[1] = packdup(bv.y);
            bd[2] = packdup(bv.z); bd[3] = packdup(bv.w);
            u64 ap[NP];
            if (TM == 32){
                ap[0] = *(const u64*)&As[kk][ty*2];
            } else if (TM == 64){
                const u64* p = (const u64*)&As[kk][ty*4];
                ap[0] = p[0]; ap[1] = p[1];
            } else {
                const u64* p0 = (const u64*)&As[kk][ty*4];
                const u64* p1 = (const u64*)&As[kk][64 + ty*4];
                ap[0] = p0[0]; ap[1] = p0[1]; ap[2] = p1[0]; ap[3] = p1[1];
            }
            #pragma unroll
            for (int p = 0; p < NP; p++)
                #pragma unroll
                for (int j = 0; j < 4; j++)
                    ffma2(acc[p][j], ap[p], bd[j]);
        }
        __syncthreads();
    }

    #pragma unroll
    for (int p = 0; p < NP; p++){
        int rbase = (TM == 32) ? ty*2
                  : (TM == 64) ? ty*4 + (p & 1)*2
                  : (p >> 1)*64 + ty*4 + (p & 1)*2;
        #pragma unroll
        for (int j = 0; j < 4; j++){
            int n = n0 + tx*4 + j;
            if (n >= N) continue;
            float lo, hi;
            unpack2(acc[p][j], lo, hi);
            #pragma unroll
            for (int half = 0; half < 2; half++){
                int mr = rbase + half;
                int m = m0 + mr;
                float v = half ? hi : lo;
                if (BIAS) v += bias[n];
                if (ACT == 2) v = 0.5f * v * (1.f + erff(v * 0.70710678118654752f));
                if (RES) v += res[(size_t)m*N + n];
                if (SPLITD)      out[(size_t)dir*L*CCH + (size_t)m*N + n] = v;
                else if (TSTORE) out[(size_t)n*L + m] = v;
                else             out[(size_t)m*N + n] = v;
                if (DELTA && n < 8) sdt[mr][n] = v;
            }
        }
    }

    if (DELTA){
        __syncthreads();
        int d = tid;
        float wr[8];
        #pragma unroll
        for (int r = 0; r < 8; r++) wr[r] = dtw[d*8 + r];
        float b = dtb[d];
        for (int tt = 0; tt < TM; tt++){
            float a = b;
            #pragma unroll
            for (int r = 0; r < 8; r++) a = fmaf(wr[r], sdt[tt][r], a);
            a = (a > 20.f) ? a : log1pf(__expf(a));
            g_delta[(size_t)(m0 + tt)*DI + d] = a;
        }
    }
}

// ---------------- Wf = proj_w[:, dir block] @ out_proj ----------------
__global__ void k_wfuse(const float* __restrict__ pw, const float* __restrict__ op){
    __shared__ float spw[3*CCH];
    int o = blockIdx.x, k = threadIdx.x;      // 128 blocks, 256 threads
    for (int i = k; i < 3*CCH; i += 256) spw[i] = pw[o*3*CCH + i];
    __syncthreads();
    float a0 = 0.f, a1 = 0.f, a2 = 0.f;
    for (int c = 0; c < CCH; c++){
        float v = op[(size_t)c*DI + k];
        a0 = fmaf(spw[c],       v, a0);
        a1 = fmaf(spw[CCH+c],   v, a1);
        a2 = fmaf(spw[2*CCH+c], v, a2);
    }
    g_wf[(size_t)o*(NDIR*DI) + k]        = a0;
    g_wf[(size_t)o*(NDIR*DI) + DI + k]   = a1;
    g_wf[(size_t)o*(NDIR*DI) + 2*DI + k] = a2;
}

// ---------------- K3: tiled causal depthwise conv + silu (512 threads) ----------------
__global__ void __launch_bounds__(512) k_conv(const float* __restrict__ cw,
                                              const float* __restrict__ cb){
    __shared__ float sx[CTL+3][DI];
    int dir = blockIdx.y, l0 = blockIdx.x*CTL;
    int ch = threadIdx.x & 255, half = threadIdx.x >> 8;
    for (int r = half; r < CTL+3; r += 2){
        int row = l0 - 3 + r;
        sx[r][ch] = (row >= 0) ? g_xz[(size_t)ptok(dir, row)*(2*DI) + ch] : 0.f;
    }
    __syncthreads();
    float w0 = cw[ch*4+0], w1 = cw[ch*4+1], w2 = cw[ch*4+2], w3 = cw[ch*4+3];
    float b = cb[ch];
    int ibeg = half*(CTL/2), iend = ibeg + CTL/2;
    for (int i = ibeg; i < iend; i++){
        float acc = b + w0*sx[i][ch] + w1*sx[i+1][ch] + w2*sx[i+2][ch] + w3*sx[i+3][ch];
        acc = acc / (1.f + __expf(-acc));
        g_xc[(size_t)(dir*L + l0 + i)*DI + ch] = acc;
    }
}

// ---------------- fused selective scan: block per (dir, d) ----------------
__global__ void __launch_bounds__(1024) k_scan(const float* __restrict__ Alog,
                                               const float* __restrict__ Dp){
    __shared__ float sP[NCHUNK][DS];
    __shared__ float sS[NCHUNK][DS];
    int bx = blockIdx.x;
    int dir = bx >> 8, d = bx & 255;
    int tid = threadIdx.x;
    int chunk = tid >> 4, n = tid & 15;
    float Av = -__expf(Alog[d*DS + n]);
    int base = dir*L + chunk*CHLEN;

    float P = 1.f, S = 0.f;
    for (int st = 0; st < CHLEN; st++){
        int lg = base + st;
        float dl = g_delta[(size_t)lg*DI + d];
        float u  = g_xc  [(size_t)lg*DI + d];
        float Bv = g_dbl [(size_t)lg*40 + 8 + n];
        float a  = __expf(dl * Av);
        P *= a;
        S = a*S + dl*Bv*u;
    }
    sP[chunk][n] = P; sS[chunk][n] = S;
    __syncthreads();

    #pragma unroll
    for (int off = 1; off < NCHUNK; off <<= 1){
        float pP = 1.f, pS = 0.f;
        if (chunk >= off){ pP = sP[chunk-off][n]; pS = sS[chunk-off][n]; }
        __syncthreads();
        S = fmaf(P, pS, S);
        P *= pP;
        sP[chunk][n] = P; sS[chunk][n] = S;
        __syncthreads();
    }
    float h = (chunk > 0) ? sS[chunk-1][n] : 0.f;

    float Dv = Dp[d];
    for (int st = 0; st < CHLEN; st++){
        int lg = base + st;
        float dl = g_delta[(size_t)lg*DI + d];
        float u  = g_xc  [(size_t)lg*DI + d];
        float Bv = g_dbl [(size_t)lg*40 + 8 + n];
        float Cv = g_dbl [(size_t)lg*40 + 24 + n];
        float a  = __expf(dl * Av);
        h = a*h + dl*Bv*u;
        float p = h * Cv;
        p += __shfl_xor_sync(0xffffffffu, p, 8);
        p += __shfl_xor_sync(0xffffffffu, p, 4);
        p += __shfl_xor_sync(0xffffffffu, p, 2);
        p += __shfl_xor_sync(0xffffffffu, p, 1);
        if (n == 0){
            int l = chunk*CHLEN + st;
            float z = g_xz[(size_t)ptok(dir, l)*(2*DI) + DI + d];
            float yy = (p + u*Dv) * (z / (1.f + __expf(-z)));
            g_y[(size_t)lg*DI + d] = yy;
        }
    }
}

// ---------------- fused: sum 3 dir-partials + bias + x residual -> resT; then LN -> tok ----------------
__device__ __forceinline__ float bsum128(float v, float* sh){
    #pragma unroll
    for (int o = 16; o; o >>= 1) v += __shfl_xor_sync(0xffffffffu, v, o);
    __syncthreads();
    if ((threadIdx.x & 31) == 0) sh[threadIdx.x >> 5] = v;
    __syncthreads();
    return sh[0] + sh[1] + sh[2] + sh[3];
}
__global__ void k_ln_res(const float* __restrict__ pb,
                         const float* __restrict__ lnw, const float* __restrict__ lnb){
    __shared__ float sh[4];
    int s = blockIdx.x, c = threadIdx.x;
    float v = g_pp[(size_t)s*CCH + c]
            + g_pp[(size_t)(L + s)*CCH + c]
            + g_pp[(size_t)(2*L + s)*CCH + c]
            + pb[c] + g_xT[(size_t)s*CCH + c];
    g_resT[(size_t)s*CCH + c] = v;
    float m   = bsum128(v, sh) * (1.f/128.f);
    float d   = v - m;
    float var = bsum128(d*d, sh) * (1.f/128.f);
    g_tok[(size_t)s*CCH + c] = d * rsqrtf(var + 1e-6f) * lnw[c] + lnb[c];
}

// ---------------- launch ----------------
extern "C" void kernel_launch(void* const* d_in, const int* in_sizes, int n_in,
                              void* d_out, int out_size){
    const float* x        = (const float*)d_in[0];
    const float* ln_w     = (const float*)d_in[1];
    const float* ln_b     = (const float*)d_in[2];
    const float* mnorm_w  = (const float*)d_in[3];
    const float* mnorm_b  = (const float*)d_in[4];
    const float* in_proj  = (const float*)d_in[5];
    const float* conv_w   = (const float*)d_in[6];
    const float* conv_b   = (const float*)d_in[7];
    const float* x_proj   = (const float*)d_in[8];
    const float* dt_proj  = (const float*)d_in[9];
    const float* dt_bias  = (const float*)d_in[10];
    const float* A_log    = (const float*)d_in[11];
    const float* D_param  = (const float*)d_in[12];
    const float* out_proj = (const float*)d_in[13];
    const float* proj_w   = (const float*)d_in[14];
    const float* proj_b   = (const float*)d_in[15];
    const float* fc1_w    = (const float*)d_in[16];
    const float* fc1_b    = (const float*)d_in[17];
    const float* fc2_w    = (const float*)d_in[18];
    const float* fc2_b    = (const float*)d_in[19];
    float* out = (float*)d_out;

    void *p_tok, *p_xz, *p_xc, *p_dbl, *p_y, *p_pp, *p_wf, *p_resT, *p_hid;
    cudaGetSymbolAddress(&p_tok,  g_tok);
    cudaGetSymbolAddress(&p_xz,   g_xz);
    cudaGetSymbolAddress(&p_xc,   g_xc);
    cudaGetSymbolAddress(&p_dbl,  g_dbl);
    cudaGetSymbolAddress(&p_y,    g_y);
    cudaGetSymbolAddress(&p_pp,   g_pp);
    cudaGetSymbolAddress(&p_wf,   g_wf);
    cudaGetSymbolAddress(&p_resT, g_resT);
    cudaGetSymbolAddress(&p_hid,  g_hid);

    // 0. fused weights Wf = proj_w_dir @ out_proj
    k_wfuse<<<CCH, 256>>>(proj_w, out_proj);
    // 1. fused transpose + double token LN
    k_lnx<<<L/32, 256>>>(x, ln_w, ln_b, mnorm_w, mnorm_b);
    // 2. in_proj: [4096,128]@[512,128]^T  (R3 config)
    k_tgemm<128,0,false,false,false,0,false,false><<<dim3(L/128, 8), 256>>>(
        (const float*)p_tok, in_proj, nullptr, nullptr, (float*)p_xz, 512, 128, 128, nullptr, nullptr);
    // 3. tiled causal conv + silu (512 threads)
    k_conv<<<dim3(L/CTL, NDIR), 512>>>(conv_w, conv_b);
    // 4. x_dbl GEMM + fused delta epilogue (TM=64)
    k_tgemm<64,0,false,false,false,0,true,false><<<dim3(LT/64, 1), 256>>>(
        (const float*)p_xc, x_proj, nullptr, nullptr, (float*)p_dbl, 40, 256, 256, dt_proj, dt_bias);
    // 5. fused selective scan
    k_scan<<<NDIR*DI, 1024>>>(A_log, D_param);
    // 6. dir-split fused (out_proj∘proj) GEMM (TM=64 -> 384 blocks)
    k_tgemm<64,0,false,false,false,2,false,true><<<dim3(L/64, 2, NDIR), 256>>>(
        (const float*)p_y, (const float*)p_wf, nullptr, nullptr, (float*)p_pp, 128, 256, NDIR*DI, nullptr, nullptr);
    // 7. sum partials + proj_b + x residual -> resT, then LN -> tok
    k_ln_res<<<L, 128>>>(proj_b, ln_w, ln_b);
    // 8. fc1 + exact GELU (R3 config)
    k_tgemm<128,2,true,false,false,0,false,false><<<dim3(L/128, 8), 256>>>(
        (const float*)p_tok, fc1_w, fc1_b, nullptr, (float*)p_hid, 512, 128, 128, nullptr, nullptr);
    // 9. fc2 + bias + residual + transposed store to (C,D,H,W) (R3 config)
    k_tgemm<32,0,true,true,true,0,false,false><<<dim3(L/32, 2), 256>>>(
        (const float*)p_hid, fc2_w, fc2_b, (const float*)p_resT, out, 128, 512, 512, nullptr, nullptr);
}